// round 14
// baseline (speedup 1.0000x reference)
#include <cuda_runtime.h>
#include <cuda_fp16.h>
#include <math.h>
#include <stdint.h>

#define B_    8
#define C_    256
#define N_    1024
#define H_    8
#define HID_  512
#define O3_   1536
#define SCALE_ 10.0f
#define EPS_   1e-12f
#define LOG2E_ 1.4426950408889634f

// Scratch (static device arrays; no allocation allowed)
__device__ float    g_sumsq[2 * B_ * HID_];
__device__ uint32_t g_xh[(size_t)B_ * C_ * N_ / 2];   // half2 x [b][c][p]
__device__ uint32_t g_wqh[O3_ * C_ / 2];              // half2 w_qkv [o][c]
__device__ uint32_t g_woh[C_ * HID_ / 2];             // half2 w_out [o][hid]
__device__ uint32_t g_qT[(size_t)B_ * H_ * N_ * 32];  // half2 q [b][h][i][d2]
__device__ uint32_t g_kT[(size_t)B_ * H_ * N_ * 32];  // half2 k [b][h][j][d2]
__device__ uint32_t g_vh[(size_t)B_ * H_ * 64 * 512]; // half2 v [b][h][d][j2]
__device__ __half   g_atth[(size_t)B_ * HID_ * N_];   // half attn out [b][hid][p]

__device__ __forceinline__ uint32_t packh2(float lo, float hi) {
    __half2 h = __floats2half2_rn(lo, hi);
    return *(uint32_t*)&h;
}
__device__ __forceinline__ uint32_t scaleh2(uint32_t v, float2 w) {
    __half2 h = *(__half2*)&v;
    float2 f = __half22float2(h);
    return packh2(f.x * w.x, f.y * w.y);
}
__device__ __forceinline__ uint32_t ex2h2(uint32_t x) {
    uint32_t r; asm("ex2.approx.f16x2 %0, %1;" : "=r"(r) : "r"(x)); return r;
}
__device__ __forceinline__ void mma_f16(float* d, const uint32_t* a, const uint32_t* b) {
    asm volatile("mma.sync.aligned.m16n8k16.row.col.f32.f16.f16.f32 "
                 "{%0,%1,%2,%3}, {%4,%5,%6,%7}, {%8,%9}, {%0,%1,%2,%3};\n"
                 : "+f"(d[0]), "+f"(d[1]), "+f"(d[2]), "+f"(d[3])
                 : "r"(a[0]), "r"(a[1]), "r"(a[2]), "r"(a[3]),
                   "r"(b[0]), "r"(b[1]));
}
// f16-accumulator mma: D (2x half2 regs) has exactly the A-fragment layout
__device__ __forceinline__ void mma_f16_s16(uint32_t* d, const uint32_t* a, const uint32_t* b) {
    asm volatile("mma.sync.aligned.m16n8k16.row.col.f16.f16.f16.f16 "
                 "{%0,%1}, {%2,%3,%4,%5}, {%6,%7}, {%0,%1};\n"
                 : "+r"(d[0]), "+r"(d[1])
                 : "r"(a[0]), "r"(a[1]), "r"(a[2]), "r"(a[3]),
                   "r"(b[0]), "r"(b[1]));
}
__device__ __forceinline__ void ldsm4(uint32_t* r, uint32_t saddr) {
    asm volatile("ldmatrix.sync.aligned.m8n8.x4.shared.b16 {%0,%1,%2,%3}, [%4];"
                 : "=r"(r[0]), "=r"(r[1]), "=r"(r[2]), "=r"(r[3]) : "r"(saddr));
}
__device__ __forceinline__ void ldsm4t(uint32_t* r, uint32_t saddr) {
    asm volatile("ldmatrix.sync.aligned.m8n8.x4.trans.shared.b16 {%0,%1,%2,%3}, [%4];"
                 : "=r"(r[0]), "=r"(r[1]), "=r"(r[2]), "=r"(r[3]) : "r"(saddr));
}
__device__ __forceinline__ void cpa16(void* dst, const void* src) {
    uint32_t d = (uint32_t)__cvta_generic_to_shared(dst);
    asm volatile("cp.async.cg.shared.global [%0], [%1], 16;" :: "r"(d), "l"(src));
}
#define CP_COMMIT() asm volatile("cp.async.commit_group;")
#define CP_WAIT(n)  asm volatile("cp.async.wait_group %0;" :: "n"(n))

// ---------------------------------------------------------------------------
// fp16 conversion of inputs + zero sumsq accumulators (float4 vectorized).
// ---------------------------------------------------------------------------
__global__ void __launch_bounds__(256) cvt_k(const float* __restrict__ x,
                                             const float* __restrict__ wq,
                                             const float* __restrict__ wo)
{
    const int i = blockIdx.x * 256 + threadIdx.x;
    const int stride = gridDim.x * 256;
    for (int t = i; t < 2 * B_ * HID_; t += stride) g_sumsq[t] = 0.f;
    for (int t = i; t < B_ * C_ * N_ / 4; t += stride) {
        float4 v = ((const float4*)x)[t];
        ((uint2*)g_xh)[t] = make_uint2(packh2(v.x, v.y), packh2(v.z, v.w));
    }
    for (int t = i; t < O3_ * C_ / 4; t += stride) {
        float4 v = ((const float4*)wq)[t];
        ((uint2*)g_wqh)[t] = make_uint2(packh2(v.x, v.y), packh2(v.z, v.w));
    }
    for (int t = i; t < C_ * HID_ / 4; t += stride) {
        float4 v = ((const float4*)wo)[t];
        ((uint2*)g_woh)[t] = make_uint2(packh2(v.x, v.y), packh2(v.z, v.w));
    }
}

// ---------------------------------------------------------------------------
// QKV projection (fp16 mma), 3-stage cp.async ring — unchanged from R10.
// ---------------------------------------------------------------------------
#define G1_ASZ (128 * 40)
#define G1_BSZ (32 * 136)
#define G1_STG (G1_ASZ + G1_BSZ)
#define G1_SMEM (3 * G1_STG * 2)

__global__ void __launch_bounds__(256) gemm_qkv()
{
    extern __shared__ __half hsm[];

    const int b = blockIdx.z;
    const int o0 = blockIdx.y * 128;
    const int p0 = blockIdx.x * 128;
    const __half* W = (const __half*)g_wqh;
    const __half* Xb = (const __half*)g_xh + (size_t)b * C_ * N_;

    const int tid = threadIdx.x, warp = tid >> 5, lane = tid & 31;
    const int g = lane >> 2, c = lane & 3;
    const int wmb = (warp >> 2) * 64;
    const int wnb = (warp & 3) * 32;
    const int lr = (lane & 7) + ((lane >> 3) & 1) * 8;
    const int hc = (lane >> 4) * 8;

    float acc[4][4][4];
#pragma unroll
    for (int mt = 0; mt < 4; mt++)
#pragma unroll
        for (int nt = 0; nt < 4; nt++)
#pragma unroll
            for (int q = 0; q < 4; q++) acc[mt][nt][q] = 0.f;

    auto load_tile = [&](int k0, int st) {
        __half* A = hsm + st * G1_STG;
        __half* Bs = A + G1_ASZ;
#pragma unroll
        for (int rep = 0; rep < 2; rep++) {
            int lin = rep * 256 + tid;
            int m = lin >> 2, ch = lin & 3;
            cpa16(A + m * 40 + ch * 8, W + (size_t)(o0 + m) * C_ + k0 + ch * 8);
        }
#pragma unroll
        for (int rep = 0; rep < 2; rep++) {
            int lin = rep * 256 + tid;
            int k = lin >> 4, ch = lin & 15;
            cpa16(Bs + k * 136 + ch * 8, Xb + (size_t)(k0 + k) * N_ + p0 + ch * 8);
        }
    };

    load_tile(0, 0); CP_COMMIT();
    load_tile(32, 1); CP_COMMIT();
    const int T = C_ / 32;
    for (int t = 0; t < T; t++) {
        if (t == T - 1) { CP_WAIT(0); } else { CP_WAIT(1); }
        __syncthreads();
        if (t + 2 < T) { load_tile((t + 2) * 32, (t + 2) % 3); CP_COMMIT(); }
        uint32_t ab = (uint32_t)__cvta_generic_to_shared(hsm + (t % 3) * G1_STG);
        uint32_t bb = ab + G1_ASZ * 2;
#pragma unroll
        for (int ks = 0; ks < 2; ks++) {
            uint32_t a[4][4];
#pragma unroll
            for (int mt = 0; mt < 4; mt++)
                ldsm4(a[mt], ab + ((wmb + mt * 16 + lr) * 40 + ks * 16 + hc) * 2);
            uint32_t bf[4][2];
#pragma unroll
            for (int np = 0; np < 2; np++) {
                uint32_t r[4];
                ldsm4t(r, bb + ((ks * 16 + lr) * 136 + wnb + np * 16 + hc) * 2);
                bf[2 * np][0] = r[0]; bf[2 * np][1] = r[1];
                bf[2 * np + 1][0] = r[2]; bf[2 * np + 1][1] = r[3];
            }
#pragma unroll
            for (int nt = 0; nt < 4; nt++)
#pragma unroll
                for (int mt = 0; mt < 4; mt++)
                    mma_f16(acc[mt][nt], a[mt], bf[nt]);
        }
    }
    __syncthreads();

    const int type = blockIdx.y >> 2;
    const int h0 = (blockIdx.y & 3) * 2;

    if (type == 2) {
#pragma unroll
        for (int mt = 0; mt < 4; mt++) {
#pragma unroll
            for (int nt = 0; nt < 4; nt++) {
                int pc2 = (p0 + wnb + nt * 8) / 2 + c;
                int ol = wmb + mt * 16 + g;
                int ha = ol >> 6, da = ol & 63;
                g_vh[((size_t)(b * H_ + h0 + ha) * 64 + da) * 512 + pc2] =
                    packh2(acc[mt][nt][0], acc[mt][nt][1]);
                int ol8 = ol + 8;
                int hb = ol8 >> 6, db = ol8 & 63;
                g_vh[((size_t)(b * H_ + h0 + hb) * 64 + db) * 512 + pc2] =
                    packh2(acc[mt][nt][2], acc[mt][nt][3]);
            }
        }
        return;
    }

    const int sbase = type * (B_ * HID_) + b * HID_ + (blockIdx.y & 3) * 128;
#pragma unroll
    for (int mt = 0; mt < 4; mt++) {
        float s0 = 0.f, s1 = 0.f;
#pragma unroll
        for (int nt = 0; nt < 4; nt++) {
            s0 = fmaf(acc[mt][nt][0], acc[mt][nt][0], s0);
            s0 = fmaf(acc[mt][nt][1], acc[mt][nt][1], s0);
            s1 = fmaf(acc[mt][nt][2], acc[mt][nt][2], s1);
            s1 = fmaf(acc[mt][nt][3], acc[mt][nt][3], s1);
        }
        s0 += __shfl_xor_sync(0xffffffffu, s0, 1);
        s0 += __shfl_xor_sync(0xffffffffu, s0, 2);
        s1 += __shfl_xor_sync(0xffffffffu, s1, 1);
        s1 += __shfl_xor_sync(0xffffffffu, s1, 2);
        if (c == 0) {
            int ol = wmb + mt * 16 + g;
            atomicAdd(&g_sumsq[sbase + ol], s0);
            atomicAdd(&g_sumsq[sbase + ol + 8], s1);
        }
    }

    __half* trs = hsm;  // [128 p][136]
#pragma unroll
    for (int mt = 0; mt < 4; mt++) {
#pragma unroll
        for (int nt = 0; nt < 4; nt++) {
            int ol = wmb + mt * 16 + g;
            int pc = wnb + nt * 8 + 2 * c;
            trs[pc * 136 + ol]           = __float2half_rn(acc[mt][nt][0]);
            trs[(pc + 1) * 136 + ol]     = __float2half_rn(acc[mt][nt][1]);
            trs[pc * 136 + ol + 8]       = __float2half_rn(acc[mt][nt][2]);
            trs[(pc + 1) * 136 + ol + 8] = __float2half_rn(acc[mt][nt][3]);
        }
    }
    __syncthreads();

    uint32_t* dst = (type == 0) ? g_qT : g_kT;
#pragma unroll
    for (int rep = 0; rep < 32; rep++) {
        int lin = rep * 256 + tid;
        int d2 = lin & 31, hh = (lin >> 5) & 1, p = lin >> 6;
        dst[((size_t)(b * H_ + h0 + hh) * N_ + p0 + p) * 32 + d2] =
            *(const uint32_t*)&trs[p * 136 + hh * 64 + 2 * d2];
    }
}

// ---------------------------------------------------------------------------
// Output projection (fp16 mma), BM=64 x BN=128 (R10 shape), 4-stage ring,
// prefetch distance 3 (CP_WAIT(2)) to cover DRAM latency.
// ---------------------------------------------------------------------------
#define G2_ASZ (64 * 40)
#define G2_BSZ (32 * 136)
#define G2_STG (G2_ASZ + G2_BSZ)
#define G2_SMEM (4 * G2_STG * 2)

__global__ void __launch_bounds__(256) gemm_out(const float* __restrict__ bias,
                                                float* __restrict__ Y)
{
    extern __shared__ __half hsm[];

    const int b = blockIdx.z;
    const int o0 = blockIdx.y * 64;
    const int p0 = blockIdx.x * 128;
    const __half* W = (const __half*)g_woh;
    const __half* Xb = g_atth + (size_t)b * HID_ * N_;
    float* Yb = Y + (size_t)b * C_ * N_;

    const int tid = threadIdx.x, warp = tid >> 5, lane = tid & 31;
    const int g = lane >> 2, c = lane & 3;
    const int wmb = (warp >> 2) * 32;
    const int wnb = (warp & 3) * 32;
    const int lr = (lane & 7) + ((lane >> 3) & 1) * 8;
    const int hc = (lane >> 4) * 8;

    float acc[2][4][4];
#pragma unroll
    for (int mt = 0; mt < 2; mt++)
#pragma unroll
        for (int nt = 0; nt < 4; nt++)
#pragma unroll
            for (int q = 0; q < 4; q++) acc[mt][nt][q] = 0.f;

    auto load_tile = [&](int k0, int st) {
        __half* A = hsm + st * G2_STG;
        __half* Bs = A + G2_ASZ;
        {
            int m = tid >> 2, ch = tid & 3;
            cpa16(A + m * 40 + ch * 8, W + (size_t)(o0 + m) * HID_ + k0 + ch * 8);
        }
#pragma unroll
        for (int rep = 0; rep < 2; rep++) {
            int lin = rep * 256 + tid;
            int k = lin >> 4, ch = lin & 15;
            cpa16(Bs + k * 136 + ch * 8, Xb + (size_t)(k0 + k) * N_ + p0 + ch * 8);
        }
    };

    load_tile(0, 0); CP_COMMIT();
    load_tile(32, 1); CP_COMMIT();
    load_tile(64, 2); CP_COMMIT();
    const int T = HID_ / 32;
    for (int t = 0; t < T; t++) {
        if (t >= T - 3) { CP_WAIT(0); } else { CP_WAIT(2); }
        __syncthreads();
        if (t + 3 < T) { load_tile((t + 3) * 32, (t + 3) & 3); CP_COMMIT(); }
        uint32_t ab = (uint32_t)__cvta_generic_to_shared(hsm + (t & 3) * G2_STG);
        uint32_t bb = ab + G2_ASZ * 2;
#pragma unroll
        for (int ks = 0; ks < 2; ks++) {
            uint32_t a[2][4];
#pragma unroll
            for (int mt = 0; mt < 2; mt++)
                ldsm4(a[mt], ab + ((wmb + mt * 16 + lr) * 40 + ks * 16 + hc) * 2);
            uint32_t bf[4][2];
#pragma unroll
            for (int np = 0; np < 2; np++) {
                uint32_t r[4];
                ldsm4t(r, bb + ((ks * 16 + lr) * 136 + wnb + np * 16 + hc) * 2);
                bf[2 * np][0] = r[0]; bf[2 * np][1] = r[1];
                bf[2 * np + 1][0] = r[2]; bf[2 * np + 1][1] = r[3];
            }
#pragma unroll
            for (int nt = 0; nt < 4; nt++)
#pragma unroll
                for (int mt = 0; mt < 2; mt++)
                    mma_f16(acc[mt][nt], a[mt], bf[nt]);
        }
    }

#pragma unroll
    for (int mt = 0; mt < 2; mt++) {
        int r0 = o0 + wmb + mt * 16 + g;
        float bv0 = bias[r0];
        float bv1 = bias[r0 + 8];
#pragma unroll
        for (int nt = 0; nt < 4; nt++) {
            int col = p0 + wnb + nt * 8 + 2 * c;
            *(float2*)(Yb + (size_t)r0 * N_ + col) =
                make_float2(acc[mt][nt][0] + bv0, acc[mt][nt][1] + bv0);
            *(float2*)(Yb + (size_t)(r0 + 8) * N_ + col) =
                make_float2(acc[mt][nt][2] + bv1, acc[mt][nt][3] + bv1);
        }
    }
}

// ---------------------------------------------------------------------------
// Fused flash attention, fp16 m16n8k16, 4 warps x 32 query rows — R10 exact.
// 3-stage K/V ring, ONE barrier per tile. Ones B-fragment in registers.
// ---------------------------------------------------------------------------
#define KV_BUF (128 * 36)
#define ATTN_SMEM_B (3 * KV_BUF * 4)

__global__ void __launch_bounds__(128, 3) attn_fp16()
{
    extern __shared__ uint32_t smem[];
    __shared__ float wsc_s[64];

    const int b = blockIdx.z, h = blockIdx.y, i0 = blockIdx.x * 128;
    const uint32_t* qTb = g_qT + (size_t)(b * H_ + h) * N_ * 32;
    const uint32_t* kTb = g_kT + (size_t)(b * H_ + h) * N_ * 32;
    const uint32_t* vhb = g_vh + (size_t)(b * H_ + h) * 64 * 512;

    const int tid = threadIdx.x;
    const int warp = tid >> 5, lane = tid & 31;
    const int g = lane >> 2, c = lane & 3;
    const int wb = warp * 32;
    const int lrB = (lane & 7) + (lane >> 4) * 8;
    const int kcB = ((lane >> 3) & 1) * 4;
    const int lrA = (lane & 7) + ((lane >> 3) & 1) * 8;
    const int kcA = (lane >> 4) * 4;

    const uint32_t sbase = (uint32_t)__cvta_generic_to_shared(smem);

    uint32_t onesf[2];
    onesf[0] = onesf[1] = (g == 0) ? 0x3C003C00u : 0u;

    auto load_kv = [&](int j0, int st) {
        uint32_t* K = smem + st * KV_BUF;
        uint32_t* V = K + 64 * 36;
#pragma unroll
        for (int rep = 0; rep < 4; rep++) {
            int lin = rep * 128 + tid;
            int r = lin >> 3, sg = (lin & 7) * 4;
            cpa16(&K[r * 36 + sg], kTb + (size_t)(j0 + r) * 32 + sg);
        }
#pragma unroll
        for (int rep = 0; rep < 4; rep++) {
            int lin = rep * 128 + tid;
            int r = lin >> 3, sg = (lin & 7) * 4;
            cpa16(&V[r * 36 + sg], vhb + (size_t)r * 512 + j0 / 2 + sg);
        }
    };

    uint32_t* Qst = smem + 2 * KV_BUF;
#pragma unroll
    for (int rep = 0; rep < 8; rep++) {
        int lin = rep * 128 + tid;
        int i = lin >> 3, sg = (lin & 7) * 4;
        cpa16(&Qst[i * 36 + sg], qTb + (size_t)(i0 + i) * 32 + sg);
    }
    CP_COMMIT();
    load_kv(0, 0); CP_COMMIT();
    load_kv(64, 1); CP_COMMIT();
    if (tid < 64) {
        float qs = g_sumsq[b * HID_ + h * 64 + tid];
        float ks = g_sumsq[B_ * HID_ + b * HID_ + h * 64 + tid];
        wsc_s[tid] = (SCALE_ * LOG2E_) /
                     (fmaxf(sqrtf(qs), EPS_) * fmaxf(sqrtf(ks), EPS_));
    }
    CP_WAIT(2);
    __syncthreads();

    uint32_t qf[2][4][4];
    {
        const uint32_t qb32 = sbase + 2 * KV_BUF * 4;
        const float2* wsc2 = (const float2*)wsc_s;
#pragma unroll
        for (int mt = 0; mt < 2; mt++) {
#pragma unroll
            for (int ks = 0; ks < 4; ks++) {
                ldsm4(qf[mt][ks], qb32 + ((wb + mt * 16 + lrA) * 36 + ks * 8 + kcA) * 4);
                float2 wA = wsc2[ks * 8 + c];
                float2 wB = wsc2[ks * 8 + 4 + c];
                qf[mt][ks][0] = scaleh2(qf[mt][ks][0], wA);
                qf[mt][ks][1] = scaleh2(qf[mt][ks][1], wA);
                qf[mt][ks][2] = scaleh2(qf[mt][ks][2], wB);
                qf[mt][ks][3] = scaleh2(qf[mt][ks][3], wB);
            }
        }
    }

    float O[2][9][4];
#pragma unroll
    for (int mt = 0; mt < 2; mt++)
#pragma unroll
        for (int dt = 0; dt < 9; dt++)
#pragma unroll
            for (int q = 0; q < 4; q++) O[mt][dt][q] = 0.f;

    for (int t = 0; t < 16; t++) {
        if (t == 15) { CP_WAIT(0); } else { CP_WAIT(1); }
        __syncthreads();
        if (t + 2 < 16) { load_kv((t + 2) * 64, (t + 2) % 3); CP_COMMIT(); }

        const uint32_t Kb32 = sbase + (t % 3) * KV_BUF * 4;
        const uint32_t Vb32 = Kb32 + 64 * 36 * 4;

        uint32_t S2[2][8][2];
#pragma unroll
        for (int mt = 0; mt < 2; mt++)
#pragma unroll
            for (int nt = 0; nt < 8; nt++) { S2[mt][nt][0] = 0u; S2[mt][nt][1] = 0u; }
#pragma unroll
        for (int ks = 0; ks < 4; ks++) {
#pragma unroll
            for (int np = 0; np < 4; np++) {
                uint32_t r[4];
                ldsm4(r, Kb32 + ((np * 16 + lrB) * 36 + ks * 8 + kcB) * 4);
                mma_f16_s16(S2[0][2 * np],     qf[0][ks], r);
                mma_f16_s16(S2[0][2 * np + 1], qf[0][ks], r + 2);
                mma_f16_s16(S2[1][2 * np],     qf[1][ks], r);
                mma_f16_s16(S2[1][2 * np + 1], qf[1][ks], r + 2);
            }
        }

#pragma unroll
        for (int mt = 0; mt < 2; mt++)
#pragma unroll
            for (int nt = 0; nt < 8; nt++) {
                S2[mt][nt][0] = ex2h2(S2[mt][nt][0]);
                S2[mt][nt][1] = ex2h2(S2[mt][nt][1]);
            }

#pragma unroll
        for (int jt = 0; jt < 4; jt++) {
            const uint32_t* a0 = &S2[0][2 * jt][0];
            const uint32_t* a1 = &S2[1][2 * jt][0];
#pragma unroll
            for (int dp = 0; dp < 4; dp++) {
                uint32_t r[4];
                ldsm4(r, Vb32 + ((dp * 16 + lrB) * 36 + jt * 8 + kcB) * 4);
                mma_f16(O[0][2 * dp], a0, r);
                mma_f16(O[0][2 * dp + 1], a0, r + 2);
                mma_f16(O[1][2 * dp], a1, r);
                mma_f16(O[1][2 * dp + 1], a1, r + 2);
            }
            mma_f16(O[0][8], a0, onesf);
            mma_f16(O[1][8], a1, onesf);
        }
    }
    __syncthreads();

    float il[2][2];
#pragma unroll
    for (int mt = 0; mt < 2; mt++) {
        il[mt][0] = 1.f / __shfl_sync(0xffffffffu, O[mt][8][0], lane & ~3);
        il[mt][1] = 1.f / __shfl_sync(0xffffffffu, O[mt][8][2], lane & ~3);
    }

    __half* Os = (__half*)smem;  // [64][136]
#pragma unroll
    for (int mt = 0; mt < 2; mt++) {
        int rb = wb + mt * 16;
#pragma unroll
        for (int dt = 0; dt < 8; dt++) {
            int d0 = dt * 8 + 2 * c;
            Os[d0 * 136 + rb + g]           = __float2half_rn(O[mt][dt][0] * il[mt][0]);
            Os[(d0 + 1) * 136 + rb + g]     = __float2half_rn(O[mt][dt][1] * il[mt][0]);
            Os[d0 * 136 + rb + g + 8]       = __float2half_rn(O[mt][dt][2] * il[mt][1]);
            Os[(d0 + 1) * 136 + rb + g + 8] = __float2half_rn(O[mt][dt][3] * il[mt][1]);
        }
    }
    __syncthreads();

#pragma unroll
    for (int rep = 0; rep < 8; rep++) {
        int lin = rep * 128 + tid;
        int d = lin >> 4, j = lin & 15;
        uint4* ob = (uint4*)(g_atth + (size_t)(b * HID_ + h * 64 + d) * N_ + i0);
        ob[j] = *(const uint4*)&Os[d * 136 + 8 * j];
    }
}

// ---------------------------------------------------------------------------
extern "C" void kernel_launch(void* const* d_in, const int* in_sizes, int n_in,
                              void* d_out, int out_size)
{
    (void)in_sizes; (void)n_in; (void)out_size;
    const float* x     = (const float*)d_in[0];
    const float* w_qkv = (const float*)d_in[1];
    const float* w_out = (const float*)d_in[2];
    const float* b_out = (const float*)d_in[3];
    float* y = (float*)d_out;

    cudaFuncSetAttribute((const void*)gemm_qkv,
                         cudaFuncAttributeMaxDynamicSharedMemorySize, G1_SMEM);
    cudaFuncSetAttribute((const void*)gemm_out,
                         cudaFuncAttributeMaxDynamicSharedMemorySize, G2_SMEM);
    cudaFuncSetAttribute((const void*)attn_fp16,
                         cudaFuncAttributeMaxDynamicSharedMemorySize, ATTN_SMEM_B);

    cvt_k<<<2048, 256>>>(x, w_qkv, w_out);
    gemm_qkv<<<dim3(N_ / 128, O3_ / 128, B_), 256, G1_SMEM>>>();
    attn_fp16<<<dim3(N_ / 128, H_, B_), 128, ATTN_SMEM_B>>>();
    gemm_out<<<dim3(N_ / 128, C_ / 64, B_), 256, G2_SMEM>>>(b_out, y);
}

// round 15
// speedup vs baseline: 1.0198x; 1.0198x over previous
#include <cuda_runtime.h>
#include <cuda_fp16.h>
#include <math.h>
#include <stdint.h>

#define B_    8
#define C_    256
#define N_    1024
#define H_    8
#define HID_  512
#define O3_   1536
#define SCALE_ 10.0f
#define EPS_   1e-12f
#define LOG2E_ 1.4426950408889634f

// Scratch (static device arrays; no allocation allowed)
__device__ float    g_sumsq[2 * B_ * HID_];
__device__ uint32_t g_xh[(size_t)B_ * C_ * N_ / 2];   // half2 x [b][c][p]
__device__ uint32_t g_wqh[O3_ * C_ / 2];              // half2 w_qkv [o][c]
__device__ uint32_t g_woh[C_ * HID_ / 2];             // half2 w_out [o][hid]
__device__ uint32_t g_qT[(size_t)B_ * H_ * N_ * 32];  // half2 q [b][h][i][d2]
__device__ uint32_t g_kT[(size_t)B_ * H_ * N_ * 32];  // half2 k [b][h][j][d2]
__device__ uint32_t g_vh[(size_t)B_ * H_ * 64 * 512]; // half2 v [b][h][d][j2]
__device__ __half   g_atth[(size_t)B_ * HID_ * N_];   // half attn out [b][hid][p]

__device__ __forceinline__ uint32_t packh2(float lo, float hi) {
    __half2 h = __floats2half2_rn(lo, hi);
    return *(uint32_t*)&h;
}
__device__ __forceinline__ uint32_t scaleh2(uint32_t v, float2 w) {
    __half2 h = *(__half2*)&v;
    float2 f = __half22float2(h);
    return packh2(f.x * w.x, f.y * w.y);
}
__device__ __forceinline__ uint32_t ex2h2(uint32_t x) {
    uint32_t r; asm("ex2.approx.f16x2 %0, %1;" : "=r"(r) : "r"(x)); return r;
}
__device__ __forceinline__ void mma_f16(float* d, const uint32_t* a, const uint32_t* b) {
    asm volatile("mma.sync.aligned.m16n8k16.row.col.f32.f16.f16.f32 "
                 "{%0,%1,%2,%3}, {%4,%5,%6,%7}, {%8,%9}, {%0,%1,%2,%3};\n"
                 : "+f"(d[0]), "+f"(d[1]), "+f"(d[2]), "+f"(d[3])
                 : "r"(a[0]), "r"(a[1]), "r"(a[2]), "r"(a[3]),
                   "r"(b[0]), "r"(b[1]));
}
// f16-accumulator mma: D (2x half2 regs) has exactly the A-fragment layout
__device__ __forceinline__ void mma_f16_s16(uint32_t* d, const uint32_t* a, const uint32_t* b) {
    asm volatile("mma.sync.aligned.m16n8k16.row.col.f16.f16.f16.f16 "
                 "{%0,%1}, {%2,%3,%4,%5}, {%6,%7}, {%0,%1};\n"
                 : "+r"(d[0]), "+r"(d[1])
                 : "r"(a[0]), "r"(a[1]), "r"(a[2]), "r"(a[3]),
                   "r"(b[0]), "r"(b[1]));
}
__device__ __forceinline__ void ldsm4(uint32_t* r, uint32_t saddr) {
    asm volatile("ldmatrix.sync.aligned.m8n8.x4.shared.b16 {%0,%1,%2,%3}, [%4];"
                 : "=r"(r[0]), "=r"(r[1]), "=r"(r[2]), "=r"(r[3]) : "r"(saddr));
}
__device__ __forceinline__ void ldsm4t(uint32_t* r, uint32_t saddr) {
    asm volatile("ldmatrix.sync.aligned.m8n8.x4.trans.shared.b16 {%0,%1,%2,%3}, [%4];"
                 : "=r"(r[0]), "=r"(r[1]), "=r"(r[2]), "=r"(r[3]) : "r"(saddr));
}
__device__ __forceinline__ void cpa16(void* dst, const void* src) {
    uint32_t d = (uint32_t)__cvta_generic_to_shared(dst);
    asm volatile("cp.async.cg.shared.global [%0], [%1], 16;" :: "r"(d), "l"(src));
}
#define CP_COMMIT() asm volatile("cp.async.commit_group;")
#define CP_WAIT(n)  asm volatile("cp.async.wait_group %0;" :: "n"(n))

// ---------------------------------------------------------------------------
// fp16 conversion of inputs + zero sumsq accumulators (float4 vectorized).
// ---------------------------------------------------------------------------
__global__ void __launch_bounds__(256) cvt_k(const float* __restrict__ x,
                                             const float* __restrict__ wq,
                                             const float* __restrict__ wo)
{
    const int i = blockIdx.x * 256 + threadIdx.x;
    const int stride = gridDim.x * 256;
    for (int t = i; t < 2 * B_ * HID_; t += stride) g_sumsq[t] = 0.f;
    for (int t = i; t < B_ * C_ * N_ / 4; t += stride) {
        float4 v = ((const float4*)x)[t];
        ((uint2*)g_xh)[t] = make_uint2(packh2(v.x, v.y), packh2(v.z, v.w));
    }
    for (int t = i; t < O3_ * C_ / 4; t += stride) {
        float4 v = ((const float4*)wq)[t];
        ((uint2*)g_wqh)[t] = make_uint2(packh2(v.x, v.y), packh2(v.z, v.w));
    }
    for (int t = i; t < C_ * HID_ / 4; t += stride) {
        float4 v = ((const float4*)wo)[t];
        ((uint2*)g_woh)[t] = make_uint2(packh2(v.x, v.y), packh2(v.z, v.w));
    }
}

// ---------------------------------------------------------------------------
// QKV projection (fp16 mma), 3-stage cp.async ring — R10 exact.
// ---------------------------------------------------------------------------
#define G1_ASZ (128 * 40)
#define G1_BSZ (32 * 136)
#define G1_STG (G1_ASZ + G1_BSZ)
#define G1_SMEM (3 * G1_STG * 2)

__global__ void __launch_bounds__(256) gemm_qkv()
{
    extern __shared__ __half hsm[];

    const int b = blockIdx.z;
    const int o0 = blockIdx.y * 128;
    const int p0 = blockIdx.x * 128;
    const __half* W = (const __half*)g_wqh;
    const __half* Xb = (const __half*)g_xh + (size_t)b * C_ * N_;

    const int tid = threadIdx.x, warp = tid >> 5, lane = tid & 31;
    const int g = lane >> 2, c = lane & 3;
    const int wmb = (warp >> 2) * 64;
    const int wnb = (warp & 3) * 32;
    const int lr = (lane & 7) + ((lane >> 3) & 1) * 8;
    const int hc = (lane >> 4) * 8;

    float acc[4][4][4];
#pragma unroll
    for (int mt = 0; mt < 4; mt++)
#pragma unroll
        for (int nt = 0; nt < 4; nt++)
#pragma unroll
            for (int q = 0; q < 4; q++) acc[mt][nt][q] = 0.f;

    auto load_tile = [&](int k0, int st) {
        __half* A = hsm + st * G1_STG;
        __half* Bs = A + G1_ASZ;
#pragma unroll
        for (int rep = 0; rep < 2; rep++) {
            int lin = rep * 256 + tid;
            int m = lin >> 2, ch = lin & 3;
            cpa16(A + m * 40 + ch * 8, W + (size_t)(o0 + m) * C_ + k0 + ch * 8);
        }
#pragma unroll
        for (int rep = 0; rep < 2; rep++) {
            int lin = rep * 256 + tid;
            int k = lin >> 4, ch = lin & 15;
            cpa16(Bs + k * 136 + ch * 8, Xb + (size_t)(k0 + k) * N_ + p0 + ch * 8);
        }
    };

    load_tile(0, 0); CP_COMMIT();
    load_tile(32, 1); CP_COMMIT();
    const int T = C_ / 32;
    for (int t = 0; t < T; t++) {
        if (t == T - 1) { CP_WAIT(0); } else { CP_WAIT(1); }
        __syncthreads();
        if (t + 2 < T) { load_tile((t + 2) * 32, (t + 2) % 3); CP_COMMIT(); }
        uint32_t ab = (uint32_t)__cvta_generic_to_shared(hsm + (t % 3) * G1_STG);
        uint32_t bb = ab + G1_ASZ * 2;
#pragma unroll
        for (int ks = 0; ks < 2; ks++) {
            uint32_t a[4][4];
#pragma unroll
            for (int mt = 0; mt < 4; mt++)
                ldsm4(a[mt], ab + ((wmb + mt * 16 + lr) * 40 + ks * 16 + hc) * 2);
            uint32_t bf[4][2];
#pragma unroll
            for (int np = 0; np < 2; np++) {
                uint32_t r[4];
                ldsm4t(r, bb + ((ks * 16 + lr) * 136 + wnb + np * 16 + hc) * 2);
                bf[2 * np][0] = r[0]; bf[2 * np][1] = r[1];
                bf[2 * np + 1][0] = r[2]; bf[2 * np + 1][1] = r[3];
            }
#pragma unroll
            for (int nt = 0; nt < 4; nt++)
#pragma unroll
                for (int mt = 0; mt < 4; mt++)
                    mma_f16(acc[mt][nt], a[mt], bf[nt]);
        }
    }
    __syncthreads();

    const int type = blockIdx.y >> 2;
    const int h0 = (blockIdx.y & 3) * 2;

    if (type == 2) {
#pragma unroll
        for (int mt = 0; mt < 4; mt++) {
#pragma unroll
            for (int nt = 0; nt < 4; nt++) {
                int pc2 = (p0 + wnb + nt * 8) / 2 + c;
                int ol = wmb + mt * 16 + g;
                int ha = ol >> 6, da = ol & 63;
                g_vh[((size_t)(b * H_ + h0 + ha) * 64 + da) * 512 + pc2] =
                    packh2(acc[mt][nt][0], acc[mt][nt][1]);
                int ol8 = ol + 8;
                int hb = ol8 >> 6, db = ol8 & 63;
                g_vh[((size_t)(b * H_ + h0 + hb) * 64 + db) * 512 + pc2] =
                    packh2(acc[mt][nt][2], acc[mt][nt][3]);
            }
        }
        return;
    }

    const int sbase = type * (B_ * HID_) + b * HID_ + (blockIdx.y & 3) * 128;
#pragma unroll
    for (int mt = 0; mt < 4; mt++) {
        float s0 = 0.f, s1 = 0.f;
#pragma unroll
        for (int nt = 0; nt < 4; nt++) {
            s0 = fmaf(acc[mt][nt][0], acc[mt][nt][0], s0);
            s0 = fmaf(acc[mt][nt][1], acc[mt][nt][1], s0);
            s1 = fmaf(acc[mt][nt][2], acc[mt][nt][2], s1);
            s1 = fmaf(acc[mt][nt][3], acc[mt][nt][3], s1);
        }
        s0 += __shfl_xor_sync(0xffffffffu, s0, 1);
        s0 += __shfl_xor_sync(0xffffffffu, s0, 2);
        s1 += __shfl_xor_sync(0xffffffffu, s1, 1);
        s1 += __shfl_xor_sync(0xffffffffu, s1, 2);
        if (c == 0) {
            int ol = wmb + mt * 16 + g;
            atomicAdd(&g_sumsq[sbase + ol], s0);
            atomicAdd(&g_sumsq[sbase + ol + 8], s1);
        }
    }

    __half* trs = hsm;  // [128 p][136]
#pragma unroll
    for (int mt = 0; mt < 4; mt++) {
#pragma unroll
        for (int nt = 0; nt < 4; nt++) {
            int ol = wmb + mt * 16 + g;
            int pc = wnb + nt * 8 + 2 * c;
            trs[pc * 136 + ol]           = __float2half_rn(acc[mt][nt][0]);
            trs[(pc + 1) * 136 + ol]     = __float2half_rn(acc[mt][nt][1]);
            trs[pc * 136 + ol + 8]       = __float2half_rn(acc[mt][nt][2]);
            trs[(pc + 1) * 136 + ol + 8] = __float2half_rn(acc[mt][nt][3]);
        }
    }
    __syncthreads();

    uint32_t* dst = (type == 0) ? g_qT : g_kT;
#pragma unroll
    for (int rep = 0; rep < 32; rep++) {
        int lin = rep * 256 + tid;
        int d2 = lin & 31, hh = (lin >> 5) & 1, p = lin >> 6;
        dst[((size_t)(b * H_ + h0 + hh) * N_ + p0 + p) * 32 + d2] =
            *(const uint32_t*)&trs[p * 136 + hh * 64 + 2 * d2];
    }
}

// ---------------------------------------------------------------------------
// Output projection (fp16 mma), BM=64 x BN=128, KT=64 (8 iters, 4 k-steps
// per barrier), 3-stage ring, prefetch distance 2. A stride 72 halves.
// ---------------------------------------------------------------------------
#define G2_ASZ (64 * 72)
#define G2_BSZ (64 * 136)
#define G2_STG (G2_ASZ + G2_BSZ)
#define G2_SMEM (3 * G2_STG * 2)

__global__ void __launch_bounds__(256) gemm_out(const float* __restrict__ bias,
                                                float* __restrict__ Y)
{
    extern __shared__ __half hsm[];

    const int b = blockIdx.z;
    const int o0 = blockIdx.y * 64;
    const int p0 = blockIdx.x * 128;
    const __half* W = (const __half*)g_woh;
    const __half* Xb = g_atth + (size_t)b * HID_ * N_;
    float* Yb = Y + (size_t)b * C_ * N_;

    const int tid = threadIdx.x, warp = tid >> 5, lane = tid & 31;
    const int g = lane >> 2, c = lane & 3;
    const int wmb = (warp >> 2) * 32;
    const int wnb = (warp & 3) * 32;
    const int lr = (lane & 7) + ((lane >> 3) & 1) * 8;
    const int hc = (lane >> 4) * 8;

    float acc[2][4][4];
#pragma unroll
    for (int mt = 0; mt < 2; mt++)
#pragma unroll
        for (int nt = 0; nt < 4; nt++)
#pragma unroll
            for (int q = 0; q < 4; q++) acc[mt][nt][q] = 0.f;

    auto load_tile = [&](int k0, int st) {
        __half* A = hsm + st * G2_STG;
        __half* Bs = A + G2_ASZ;
#pragma unroll
        for (int rep = 0; rep < 2; rep++) {
            int lin = rep * 256 + tid;
            int m = lin >> 3, ch = lin & 7;
            cpa16(A + m * 72 + ch * 8, W + (size_t)(o0 + m) * HID_ + k0 + ch * 8);
        }
#pragma unroll
        for (int rep = 0; rep < 4; rep++) {
            int lin = rep * 256 + tid;
            int k = lin >> 4, ch = lin & 15;
            cpa16(Bs + k * 136 + ch * 8, Xb + (size_t)(k0 + k) * N_ + p0 + ch * 8);
        }
    };

    load_tile(0, 0); CP_COMMIT();
    load_tile(64, 1); CP_COMMIT();
    const int T = HID_ / 64;   // 8 iterations
    for (int t = 0; t < T; t++) {
        if (t == T - 1) { CP_WAIT(0); } else { CP_WAIT(1); }
        __syncthreads();
        if (t + 2 < T) { load_tile((t + 2) * 64, (t + 2) % 3); CP_COMMIT(); }
        uint32_t ab = (uint32_t)__cvta_generic_to_shared(hsm + (t % 3) * G2_STG);
        uint32_t bb = ab + G2_ASZ * 2;
#pragma unroll
        for (int ks = 0; ks < 4; ks++) {
            uint32_t a[2][4];
#pragma unroll
            for (int mt = 0; mt < 2; mt++)
                ldsm4(a[mt], ab + ((wmb + mt * 16 + lr) * 72 + ks * 16 + hc) * 2);
            uint32_t bf[4][2];
#pragma unroll
            for (int np = 0; np < 2; np++) {
                uint32_t r[4];
                ldsm4t(r, bb + ((ks * 16 + lr) * 136 + wnb + np * 16 + hc) * 2);
                bf[2 * np][0] = r[0]; bf[2 * np][1] = r[1];
                bf[2 * np + 1][0] = r[2]; bf[2 * np + 1][1] = r[3];
            }
#pragma unroll
            for (int nt = 0; nt < 4; nt++)
#pragma unroll
                for (int mt = 0; mt < 2; mt++)
                    mma_f16(acc[mt][nt], a[mt], bf[nt]);
        }
    }

#pragma unroll
    for (int mt = 0; mt < 2; mt++) {
        int r0 = o0 + wmb + mt * 16 + g;
        float bv0 = bias[r0];
        float bv1 = bias[r0 + 8];
#pragma unroll
        for (int nt = 0; nt < 4; nt++) {
            int col = p0 + wnb + nt * 8 + 2 * c;
            *(float2*)(Yb + (size_t)r0 * N_ + col) =
                make_float2(acc[mt][nt][0] + bv0, acc[mt][nt][1] + bv0);
            *(float2*)(Yb + (size_t)(r0 + 8) * N_ + col) =
                make_float2(acc[mt][nt][2] + bv1, acc[mt][nt][3] + bv1);
        }
    }
}

// ---------------------------------------------------------------------------
// Fused flash attention, fp16 m16n8k16, 4 warps x 32 query rows — R10 exact.
// 3-stage K/V ring, ONE barrier per tile. Ones B-fragment in registers.
// ---------------------------------------------------------------------------
#define KV_BUF (128 * 36)
#define ATTN_SMEM_B (3 * KV_BUF * 4)

__global__ void __launch_bounds__(128, 3) attn_fp16()
{
    extern __shared__ uint32_t smem[];
    __shared__ float wsc_s[64];

    const int b = blockIdx.z, h = blockIdx.y, i0 = blockIdx.x * 128;
    const uint32_t* qTb = g_qT + (size_t)(b * H_ + h) * N_ * 32;
    const uint32_t* kTb = g_kT + (size_t)(b * H_ + h) * N_ * 32;
    const uint32_t* vhb = g_vh + (size_t)(b * H_ + h) * 64 * 512;

    const int tid = threadIdx.x;
    const int warp = tid >> 5, lane = tid & 31;
    const int g = lane >> 2, c = lane & 3;
    const int wb = warp * 32;
    const int lrB = (lane & 7) + (lane >> 4) * 8;
    const int kcB = ((lane >> 3) & 1) * 4;
    const int lrA = (lane & 7) + ((lane >> 3) & 1) * 8;
    const int kcA = (lane >> 4) * 4;

    const uint32_t sbase = (uint32_t)__cvta_generic_to_shared(smem);

    uint32_t onesf[2];
    onesf[0] = onesf[1] = (g == 0) ? 0x3C003C00u : 0u;

    auto load_kv = [&](int j0, int st) {
        uint32_t* K = smem + st * KV_BUF;
        uint32_t* V = K + 64 * 36;
#pragma unroll
        for (int rep = 0; rep < 4; rep++) {
            int lin = rep * 128 + tid;
            int r = lin >> 3, sg = (lin & 7) * 4;
            cpa16(&K[r * 36 + sg], kTb + (size_t)(j0 + r) * 32 + sg);
        }
#pragma unroll
        for (int rep = 0; rep < 4; rep++) {
            int lin = rep * 128 + tid;
            int r = lin >> 3, sg = (lin & 7) * 4;
            cpa16(&V[r * 36 + sg], vhb + (size_t)r * 512 + j0 / 2 + sg);
        }
    };

    uint32_t* Qst = smem + 2 * KV_BUF;
#pragma unroll
    for (int rep = 0; rep < 8; rep++) {
        int lin = rep * 128 + tid;
        int i = lin >> 3, sg = (lin & 7) * 4;
        cpa16(&Qst[i * 36 + sg], qTb + (size_t)(i0 + i) * 32 + sg);
    }
    CP_COMMIT();
    load_kv(0, 0); CP_COMMIT();
    load_kv(64, 1); CP_COMMIT();
    if (tid < 64) {
        float qs = g_sumsq[b * HID_ + h * 64 + tid];
        float ks = g_sumsq[B_ * HID_ + b * HID_ + h * 64 + tid];
        wsc_s[tid] = (SCALE_ * LOG2E_) /
                     (fmaxf(sqrtf(qs), EPS_) * fmaxf(sqrtf(ks), EPS_));
    }
    CP_WAIT(2);
    __syncthreads();

    uint32_t qf[2][4][4];
    {
        const uint32_t qb32 = sbase + 2 * KV_BUF * 4;
        const float2* wsc2 = (const float2*)wsc_s;
#pragma unroll
        for (int mt = 0; mt < 2; mt++) {
#pragma unroll
            for (int ks = 0; ks < 4; ks++) {
                ldsm4(qf[mt][ks], qb32 + ((wb + mt * 16 + lrA) * 36 + ks * 8 + kcA) * 4);
                float2 wA = wsc2[ks * 8 + c];
                float2 wB = wsc2[ks * 8 + 4 + c];
                qf[mt][ks][0] = scaleh2(qf[mt][ks][0], wA);
                qf[mt][ks][1] = scaleh2(qf[mt][ks][1], wA);
                qf[mt][ks][2] = scaleh2(qf[mt][ks][2], wB);
                qf[mt][ks][3] = scaleh2(qf[mt][ks][3], wB);
            }
        }
    }

    float O[2][9][4];
#pragma unroll
    for (int mt = 0; mt < 2; mt++)
#pragma unroll
        for (int dt = 0; dt < 9; dt++)
#pragma unroll
            for (int q = 0; q < 4; q++) O[mt][dt][q] = 0.f;

    for (int t = 0; t < 16; t++) {
        if (t == 15) { CP_WAIT(0); } else { CP_WAIT(1); }
        __syncthreads();
        if (t + 2 < 16) { load_kv((t + 2) * 64, (t + 2) % 3); CP_COMMIT(); }

        const uint32_t Kb32 = sbase + (t % 3) * KV_BUF * 4;
        const uint32_t Vb32 = Kb32 + 64 * 36 * 4;

        uint32_t S2[2][8][2];
#pragma unroll
        for (int mt = 0; mt < 2; mt++)
#pragma unroll
            for (int nt = 0; nt < 8; nt++) { S2[mt][nt][0] = 0u; S2[mt][nt][1] = 0u; }
#pragma unroll
        for (int ks = 0; ks < 4; ks++) {
#pragma unroll
            for (int np = 0; np < 4; np++) {
                uint32_t r[4];
                ldsm4(r, Kb32 + ((np * 16 + lrB) * 36 + ks * 8 + kcB) * 4);
                mma_f16_s16(S2[0][2 * np],     qf[0][ks], r);
                mma_f16_s16(S2[0][2 * np + 1], qf[0][ks], r + 2);
                mma_f16_s16(S2[1][2 * np],     qf[1][ks], r);
                mma_f16_s16(S2[1][2 * np + 1], qf[1][ks], r + 2);
            }
        }

#pragma unroll
        for (int mt = 0; mt < 2; mt++)
#pragma unroll
            for (int nt = 0; nt < 8; nt++) {
                S2[mt][nt][0] = ex2h2(S2[mt][nt][0]);
                S2[mt][nt][1] = ex2h2(S2[mt][nt][1]);
            }

#pragma unroll
        for (int jt = 0; jt < 4; jt++) {
            const uint32_t* a0 = &S2[0][2 * jt][0];
            const uint32_t* a1 = &S2[1][2 * jt][0];
#pragma unroll
            for (int dp = 0; dp < 4; dp++) {
                uint32_t r[4];
                ldsm4(r, Vb32 + ((dp * 16 + lrB) * 36 + jt * 8 + kcB) * 4);
                mma_f16(O[0][2 * dp], a0, r);
                mma_f16(O[0][2 * dp + 1], a0, r + 2);
                mma_f16(O[1][2 * dp], a1, r);
                mma_f16(O[1][2 * dp + 1], a1, r + 2);
            }
            mma_f16(O[0][8], a0, onesf);
            mma_f16(O[1][8], a1, onesf);
        }
    }
    __syncthreads();

    float il[2][2];
#pragma unroll
    for (int mt = 0; mt < 2; mt++) {
        il[mt][0] = 1.f / __shfl_sync(0xffffffffu, O[mt][8][0], lane & ~3);
        il[mt][1] = 1.f / __shfl_sync(0xffffffffu, O[mt][8][2], lane & ~3);
    }

    __half* Os = (__half*)smem;  // [64][136]
#pragma unroll
    for (int mt = 0; mt < 2; mt++) {
        int rb = wb + mt * 16;
#pragma unroll
        for (int dt = 0; dt < 8; dt++) {
            int d0 = dt * 8 + 2 * c;
            Os[d0 * 136 + rb + g]           = __float2half_rn(O[mt][dt][0] * il[mt][0]);
            Os[(d0 + 1) * 136 + rb + g]     = __float2half_rn(O[mt][dt][1] * il[mt][0]);
            Os[d0 * 136 + rb + g + 8]       = __float2half_rn(O[mt][dt][2] * il[mt][1]);
            Os[(d0 + 1) * 136 + rb + g + 8] = __float2half_rn(O[mt][dt][3] * il[mt][1]);
        }
    }
    __syncthreads();

#pragma unroll
    for (int rep = 0; rep < 8; rep++) {
        int lin = rep * 128 + tid;
        int d = lin >> 4, j = lin & 15;
        uint4* ob = (uint4*)(g_atth + (size_t)(b * HID_ + h * 64 + d) * N_ + i0);
        ob[j] = *(const uint4*)&Os[d * 136 + 8 * j];
    }
}

// ---------------------------------------------------------------------------
extern "C" void kernel_launch(void* const* d_in, const int* in_sizes, int n_in,
                              void* d_out, int out_size)
{
    (void)in_sizes; (void)n_in; (void)out_size;
    const float* x     = (const float*)d_in[0];
    const float* w_qkv = (const float*)d_in[1];
    const float* w_out = (const float*)d_in[2];
    const float* b_out = (const float*)d_in[3];
    float* y = (float*)d_out;

    cudaFuncSetAttribute((const void*)gemm_qkv,
                         cudaFuncAttributeMaxDynamicSharedMemorySize, G1_SMEM);
    cudaFuncSetAttribute((const void*)gemm_out,
                         cudaFuncAttributeMaxDynamicSharedMemorySize, G2_SMEM);
    cudaFuncSetAttribute((const void*)attn_fp16,
                         cudaFuncAttributeMaxDynamicSharedMemorySize, ATTN_SMEM_B);

    cvt_k<<<2048, 256>>>(x, w_qkv, w_out);
    gemm_qkv<<<dim3(N_ / 128, O3_ / 128, B_), 256, G1_SMEM>>>();
    attn_fp16<<<dim3(N_ / 128, H_, B_), 128, ATTN_SMEM_B>>>();
    gemm_out<<<dim3(N_ / 128, C_ / 64, B_), 256, G2_SMEM>>>(b_out, y);
}

// round 16
// speedup vs baseline: 1.0222x; 1.0023x over previous
#include <cuda_runtime.h>
#include <cuda_fp16.h>
#include <math.h>
#include <stdint.h>

#define B_    8
#define C_    256
#define N_    1024
#define H_    8
#define HID_  512
#define O3_   1536
#define SCALE_ 10.0f
#define EPS_   1e-12f
#define LOG2E_ 1.4426950408889634f

// Scratch (static device arrays; no allocation allowed)
__device__ float    g_sumsq[2 * B_ * HID_];
__device__ uint32_t g_xh[(size_t)B_ * C_ * N_ / 2];   // half2 x [b][c][p]
__device__ uint32_t g_wqh[O3_ * C_ / 2];              // half2 w_qkv [o][c]
__device__ uint32_t g_woh[C_ * HID_ / 2];             // half2 w_out [o][hid]
__device__ uint32_t g_qT[(size_t)B_ * H_ * N_ * 32];  // half2 q [b][h][i][d2]
__device__ uint32_t g_kT[(size_t)B_ * H_ * N_ * 32];  // half2 k [b][h][j][d2]
__device__ uint32_t g_vh[(size_t)B_ * H_ * 64 * 512]; // half2 v [b][h][d][j2]
__device__ __half   g_atth[(size_t)B_ * HID_ * N_];   // half attn out [b][hid][p]

__device__ __forceinline__ uint32_t packh2(float lo, float hi) {
    __half2 h = __floats2half2_rn(lo, hi);
    return *(uint32_t*)&h;
}
__device__ __forceinline__ uint32_t scaleh2(uint32_t v, float2 w) {
    __half2 h = *(__half2*)&v;
    float2 f = __half22float2(h);
    return packh2(f.x * w.x, f.y * w.y);
}
__device__ __forceinline__ uint32_t ex2h2(uint32_t x) {
    uint32_t r; asm("ex2.approx.f16x2 %0, %1;" : "=r"(r) : "r"(x)); return r;
}
__device__ __forceinline__ void mma_f16(float* d, const uint32_t* a, const uint32_t* b) {
    asm volatile("mma.sync.aligned.m16n8k16.row.col.f32.f16.f16.f32 "
                 "{%0,%1,%2,%3}, {%4,%5,%6,%7}, {%8,%9}, {%0,%1,%2,%3};\n"
                 : "+f"(d[0]), "+f"(d[1]), "+f"(d[2]), "+f"(d[3])
                 : "r"(a[0]), "r"(a[1]), "r"(a[2]), "r"(a[3]),
                   "r"(b[0]), "r"(b[1]));
}
// f16-accumulator mma: D (2x half2 regs) has exactly the A-fragment layout
__device__ __forceinline__ void mma_f16_s16(uint32_t* d, const uint32_t* a, const uint32_t* b) {
    asm volatile("mma.sync.aligned.m16n8k16.row.col.f16.f16.f16.f16 "
                 "{%0,%1}, {%2,%3,%4,%5}, {%6,%7}, {%0,%1};\n"
                 : "+r"(d[0]), "+r"(d[1])
                 : "r"(a[0]), "r"(a[1]), "r"(a[2]), "r"(a[3]),
                   "r"(b[0]), "r"(b[1]));
}
__device__ __forceinline__ void ldsm4(uint32_t* r, uint32_t saddr) {
    asm volatile("ldmatrix.sync.aligned.m8n8.x4.shared.b16 {%0,%1,%2,%3}, [%4];"
                 : "=r"(r[0]), "=r"(r[1]), "=r"(r[2]), "=r"(r[3]) : "r"(saddr));
}
__device__ __forceinline__ void ldsm4t(uint32_t* r, uint32_t saddr) {
    asm volatile("ldmatrix.sync.aligned.m8n8.x4.trans.shared.b16 {%0,%1,%2,%3}, [%4];"
                 : "=r"(r[0]), "=r"(r[1]), "=r"(r[2]), "=r"(r[3]) : "r"(saddr));
}
__device__ __forceinline__ void cpa16(void* dst, const void* src) {
    uint32_t d = (uint32_t)__cvta_generic_to_shared(dst);
    asm volatile("cp.async.cg.shared.global [%0], [%1], 16;" :: "r"(d), "l"(src));
}
#define CP_COMMIT() asm volatile("cp.async.commit_group;")
#define CP_WAIT(n)  asm volatile("cp.async.wait_group %0;" :: "n"(n))

// ---------------------------------------------------------------------------
// fp16 conversion of inputs + zero sumsq accumulators (float4 vectorized).
// ---------------------------------------------------------------------------
__global__ void __launch_bounds__(256) cvt_k(const float* __restrict__ x,
                                             const float* __restrict__ wq,
                                             const float* __restrict__ wo)
{
    const int i = blockIdx.x * 256 + threadIdx.x;
    const int stride = gridDim.x * 256;
    for (int t = i; t < 2 * B_ * HID_; t += stride) g_sumsq[t] = 0.f;
    for (int t = i; t < B_ * C_ * N_ / 4; t += stride) {
        float4 v = ((const float4*)x)[t];
        ((uint2*)g_xh)[t] = make_uint2(packh2(v.x, v.y), packh2(v.z, v.w));
    }
    for (int t = i; t < O3_ * C_ / 4; t += stride) {
        float4 v = ((const float4*)wq)[t];
        ((uint2*)g_wqh)[t] = make_uint2(packh2(v.x, v.y), packh2(v.z, v.w));
    }
    for (int t = i; t < C_ * HID_ / 4; t += stride) {
        float4 v = ((const float4*)wo)[t];
        ((uint2*)g_woh)[t] = make_uint2(packh2(v.x, v.y), packh2(v.z, v.w));
    }
}

// ---------------------------------------------------------------------------
// QKV projection (fp16 mma), 3-stage cp.async ring — R10 exact.
// Fused epilogue: q,k -> fp16 [token][d] + sumsq atomics; v -> [d][token].
// ---------------------------------------------------------------------------
#define G1_ASZ (128 * 40)
#define G1_BSZ (32 * 136)
#define G1_STG (G1_ASZ + G1_BSZ)
#define G1_SMEM (3 * G1_STG * 2)

__global__ void __launch_bounds__(256) gemm_qkv()
{
    extern __shared__ __half hsm[];

    const int b = blockIdx.z;
    const int o0 = blockIdx.y * 128;
    const int p0 = blockIdx.x * 128;
    const __half* W = (const __half*)g_wqh;
    const __half* Xb = (const __half*)g_xh + (size_t)b * C_ * N_;

    const int tid = threadIdx.x, warp = tid >> 5, lane = tid & 31;
    const int g = lane >> 2, c = lane & 3;
    const int wmb = (warp >> 2) * 64;
    const int wnb = (warp & 3) * 32;
    const int lr = (lane & 7) + ((lane >> 3) & 1) * 8;
    const int hc = (lane >> 4) * 8;

    float acc[4][4][4];
#pragma unroll
    for (int mt = 0; mt < 4; mt++)
#pragma unroll
        for (int nt = 0; nt < 4; nt++)
#pragma unroll
            for (int q = 0; q < 4; q++) acc[mt][nt][q] = 0.f;

    auto load_tile = [&](int k0, int st) {
        __half* A = hsm + st * G1_STG;
        __half* Bs = A + G1_ASZ;
#pragma unroll
        for (int rep = 0; rep < 2; rep++) {
            int lin = rep * 256 + tid;
            int m = lin >> 2, ch = lin & 3;
            cpa16(A + m * 40 + ch * 8, W + (size_t)(o0 + m) * C_ + k0 + ch * 8);
        }
#pragma unroll
        for (int rep = 0; rep < 2; rep++) {
            int lin = rep * 256 + tid;
            int k = lin >> 4, ch = lin & 15;
            cpa16(Bs + k * 136 + ch * 8, Xb + (size_t)(k0 + k) * N_ + p0 + ch * 8);
        }
    };

    load_tile(0, 0); CP_COMMIT();
    load_tile(32, 1); CP_COMMIT();
    const int T = C_ / 32;
    for (int t = 0; t < T; t++) {
        if (t == T - 1) { CP_WAIT(0); } else { CP_WAIT(1); }
        __syncthreads();
        if (t + 2 < T) { load_tile((t + 2) * 32, (t + 2) % 3); CP_COMMIT(); }
        uint32_t ab = (uint32_t)__cvta_generic_to_shared(hsm + (t % 3) * G1_STG);
        uint32_t bb = ab + G1_ASZ * 2;
#pragma unroll
        for (int ks = 0; ks < 2; ks++) {
            uint32_t a[4][4];
#pragma unroll
            for (int mt = 0; mt < 4; mt++)
                ldsm4(a[mt], ab + ((wmb + mt * 16 + lr) * 40 + ks * 16 + hc) * 2);
            uint32_t bf[4][2];
#pragma unroll
            for (int np = 0; np < 2; np++) {
                uint32_t r[4];
                ldsm4t(r, bb + ((ks * 16 + lr) * 136 + wnb + np * 16 + hc) * 2);
                bf[2 * np][0] = r[0]; bf[2 * np][1] = r[1];
                bf[2 * np + 1][0] = r[2]; bf[2 * np + 1][1] = r[3];
            }
#pragma unroll
            for (int nt = 0; nt < 4; nt++)
#pragma unroll
                for (int mt = 0; mt < 4; mt++)
                    mma_f16(acc[mt][nt], a[mt], bf[nt]);
        }
    }
    __syncthreads();

    const int type = blockIdx.y >> 2;
    const int h0 = (blockIdx.y & 3) * 2;

    if (type == 2) {
#pragma unroll
        for (int mt = 0; mt < 4; mt++) {
#pragma unroll
            for (int nt = 0; nt < 4; nt++) {
                int pc2 = (p0 + wnb + nt * 8) / 2 + c;
                int ol = wmb + mt * 16 + g;
                int ha = ol >> 6, da = ol & 63;
                g_vh[((size_t)(b * H_ + h0 + ha) * 64 + da) * 512 + pc2] =
                    packh2(acc[mt][nt][0], acc[mt][nt][1]);
                int ol8 = ol + 8;
                int hb = ol8 >> 6, db = ol8 & 63;
                g_vh[((size_t)(b * H_ + h0 + hb) * 64 + db) * 512 + pc2] =
                    packh2(acc[mt][nt][2], acc[mt][nt][3]);
            }
        }
        return;
    }

    const int sbase = type * (B_ * HID_) + b * HID_ + (blockIdx.y & 3) * 128;
#pragma unroll
    for (int mt = 0; mt < 4; mt++) {
        float s0 = 0.f, s1 = 0.f;
#pragma unroll
        for (int nt = 0; nt < 4; nt++) {
            s0 = fmaf(acc[mt][nt][0], acc[mt][nt][0], s0);
            s0 = fmaf(acc[mt][nt][1], acc[mt][nt][1], s0);
            s1 = fmaf(acc[mt][nt][2], acc[mt][nt][2], s1);
            s1 = fmaf(acc[mt][nt][3], acc[mt][nt][3], s1);
        }
        s0 += __shfl_xor_sync(0xffffffffu, s0, 1);
        s0 += __shfl_xor_sync(0xffffffffu, s0, 2);
        s1 += __shfl_xor_sync(0xffffffffu, s1, 1);
        s1 += __shfl_xor_sync(0xffffffffu, s1, 2);
        if (c == 0) {
            int ol = wmb + mt * 16 + g;
            atomicAdd(&g_sumsq[sbase + ol], s0);
            atomicAdd(&g_sumsq[sbase + ol + 8], s1);
        }
    }

    __half* trs = hsm;  // [128 p][136]
#pragma unroll
    for (int mt = 0; mt < 4; mt++) {
#pragma unroll
        for (int nt = 0; nt < 4; nt++) {
            int ol = wmb + mt * 16 + g;
            int pc = wnb + nt * 8 + 2 * c;
            trs[pc * 136 + ol]           = __float2half_rn(acc[mt][nt][0]);
            trs[(pc + 1) * 136 + ol]     = __float2half_rn(acc[mt][nt][1]);
            trs[pc * 136 + ol + 8]       = __float2half_rn(acc[mt][nt][2]);
            trs[(pc + 1) * 136 + ol + 8] = __float2half_rn(acc[mt][nt][3]);
        }
    }
    __syncthreads();

    uint32_t* dst = (type == 0) ? g_qT : g_kT;
#pragma unroll
    for (int rep = 0; rep < 32; rep++) {
        int lin = rep * 256 + tid;
        int d2 = lin & 31, hh = (lin >> 5) & 1, p = lin >> 6;
        dst[((size_t)(b * H_ + h0 + hh) * N_ + p0 + p) * 32 + d2] =
            *(const uint32_t*)&trs[p * 136 + hh * 64 + 2 * d2];
    }
}

// ---------------------------------------------------------------------------
// Output projection (fp16 mma), BM=64 x BN=128, KT=32, 3-stage ring,
// prefetch distance 2 — R10 exact (best measured: 13.1-13.3 us).
// ---------------------------------------------------------------------------
#define G2_ASZ (64 * 40)
#define G2_BSZ (32 * 136)
#define G2_STG (G2_ASZ + G2_BSZ)
#define G2_SMEM (3 * G2_STG * 2)

__global__ void __launch_bounds__(256) gemm_out(const float* __restrict__ bias,
                                                float* __restrict__ Y)
{
    extern __shared__ __half hsm[];

    const int b = blockIdx.z;
    const int o0 = blockIdx.y * 64;
    const int p0 = blockIdx.x * 128;
    const __half* W = (const __half*)g_woh;
    const __half* Xb = g_atth + (size_t)b * HID_ * N_;
    float* Yb = Y + (size_t)b * C_ * N_;

    const int tid = threadIdx.x, warp = tid >> 5, lane = tid & 31;
    const int g = lane >> 2, c = lane & 3;
    const int wmb = (warp >> 2) * 32;
    const int wnb = (warp & 3) * 32;
    const int lr = (lane & 7) + ((lane >> 3) & 1) * 8;
    const int hc = (lane >> 4) * 8;

    float acc[2][4][4];
#pragma unroll
    for (int mt = 0; mt < 2; mt++)
#pragma unroll
        for (int nt = 0; nt < 4; nt++)
#pragma unroll
            for (int q = 0; q < 4; q++) acc[mt][nt][q] = 0.f;

    auto load_tile = [&](int k0, int st) {
        __half* A = hsm + st * G2_STG;
        __half* Bs = A + G2_ASZ;
        {
            int m = tid >> 2, ch = tid & 3;
            cpa16(A + m * 40 + ch * 8, W + (size_t)(o0 + m) * HID_ + k0 + ch * 8);
        }
#pragma unroll
        for (int rep = 0; rep < 2; rep++) {
            int lin = rep * 256 + tid;
            int k = lin >> 4, ch = lin & 15;
            cpa16(Bs + k * 136 + ch * 8, Xb + (size_t)(k0 + k) * N_ + p0 + ch * 8);
        }
    };

    load_tile(0, 0); CP_COMMIT();
    load_tile(32, 1); CP_COMMIT();
    const int T = HID_ / 32;
    for (int t = 0; t < T; t++) {
        if (t == T - 1) { CP_WAIT(0); } else { CP_WAIT(1); }
        __syncthreads();
        if (t + 2 < T) { load_tile((t + 2) * 32, (t + 2) % 3); CP_COMMIT(); }
        uint32_t ab = (uint32_t)__cvta_generic_to_shared(hsm + (t % 3) * G2_STG);
        uint32_t bb = ab + G2_ASZ * 2;
#pragma unroll
        for (int ks = 0; ks < 2; ks++) {
            uint32_t a[2][4];
#pragma unroll
            for (int mt = 0; mt < 2; mt++)
                ldsm4(a[mt], ab + ((wmb + mt * 16 + lr) * 40 + ks * 16 + hc) * 2);
            uint32_t bf[4][2];
#pragma unroll
            for (int np = 0; np < 2; np++) {
                uint32_t r[4];
                ldsm4t(r, bb + ((ks * 16 + lr) * 136 + wnb + np * 16 + hc) * 2);
                bf[2 * np][0] = r[0]; bf[2 * np][1] = r[1];
                bf[2 * np + 1][0] = r[2]; bf[2 * np + 1][1] = r[3];
            }
#pragma unroll
            for (int nt = 0; nt < 4; nt++)
#pragma unroll
                for (int mt = 0; mt < 2; mt++)
                    mma_f16(acc[mt][nt], a[mt], bf[nt]);
        }
    }

#pragma unroll
    for (int mt = 0; mt < 2; mt++) {
        int r0 = o0 + wmb + mt * 16 + g;
        float bv0 = bias[r0];
        float bv1 = bias[r0 + 8];
#pragma unroll
        for (int nt = 0; nt < 4; nt++) {
            int col = p0 + wnb + nt * 8 + 2 * c;
            *(float2*)(Yb + (size_t)r0 * N_ + col) =
                make_float2(acc[mt][nt][0] + bv0, acc[mt][nt][1] + bv0);
            *(float2*)(Yb + (size_t)(r0 + 8) * N_ + col) =
                make_float2(acc[mt][nt][2] + bv1, acc[mt][nt][3] + bv1);
        }
    }
}

// ---------------------------------------------------------------------------
// Fused flash attention, fp16 m16n8k16, 4 warps x 32 query rows — R10 exact.
// 3-stage K/V ring, ONE barrier per tile. Ones B-fragment in registers.
// ---------------------------------------------------------------------------
#define KV_BUF (128 * 36)
#define ATTN_SMEM_B (3 * KV_BUF * 4)

__global__ void __launch_bounds__(128, 3) attn_fp16()
{
    extern __shared__ uint32_t smem[];
    __shared__ float wsc_s[64];

    const int b = blockIdx.z, h = blockIdx.y, i0 = blockIdx.x * 128;
    const uint32_t* qTb = g_qT + (size_t)(b * H_ + h) * N_ * 32;
    const uint32_t* kTb = g_kT + (size_t)(b * H_ + h) * N_ * 32;
    const uint32_t* vhb = g_vh + (size_t)(b * H_ + h) * 64 * 512;

    const int tid = threadIdx.x;
    const int warp = tid >> 5, lane = tid & 31;
    const int g = lane >> 2, c = lane & 3;
    const int wb = warp * 32;
    const int lrB = (lane & 7) + (lane >> 4) * 8;
    const int kcB = ((lane >> 3) & 1) * 4;
    const int lrA = (lane & 7) + ((lane >> 3) & 1) * 8;
    const int kcA = (lane >> 4) * 4;

    const uint32_t sbase = (uint32_t)__cvta_generic_to_shared(smem);

    uint32_t onesf[2];
    onesf[0] = onesf[1] = (g == 0) ? 0x3C003C00u : 0u;

    auto load_kv = [&](int j0, int st) {
        uint32_t* K = smem + st * KV_BUF;
        uint32_t* V = K + 64 * 36;
#pragma unroll
        for (int rep = 0; rep < 4; rep++) {
            int lin = rep * 128 + tid;
            int r = lin >> 3, sg = (lin & 7) * 4;
            cpa16(&K[r * 36 + sg], kTb + (size_t)(j0 + r) * 32 + sg);
        }
#pragma unroll
        for (int rep = 0; rep < 4; rep++) {
            int lin = rep * 128 + tid;
            int r = lin >> 3, sg = (lin & 7) * 4;
            cpa16(&V[r * 36 + sg], vhb + (size_t)r * 512 + j0 / 2 + sg);
        }
    };

    uint32_t* Qst = smem + 2 * KV_BUF;
#pragma unroll
    for (int rep = 0; rep < 8; rep++) {
        int lin = rep * 128 + tid;
        int i = lin >> 3, sg = (lin & 7) * 4;
        cpa16(&Qst[i * 36 + sg], qTb + (size_t)(i0 + i) * 32 + sg);
    }
    CP_COMMIT();
    load_kv(0, 0); CP_COMMIT();
    load_kv(64, 1); CP_COMMIT();
    if (tid < 64) {
        float qs = g_sumsq[b * HID_ + h * 64 + tid];
        float ks = g_sumsq[B_ * HID_ + b * HID_ + h * 64 + tid];
        wsc_s[tid] = (SCALE_ * LOG2E_) /
                     (fmaxf(sqrtf(qs), EPS_) * fmaxf(sqrtf(ks), EPS_));
    }
    CP_WAIT(2);
    __syncthreads();

    uint32_t qf[2][4][4];
    {
        const uint32_t qb32 = sbase + 2 * KV_BUF * 4;
        const float2* wsc2 = (const float2*)wsc_s;
#pragma unroll
        for (int mt = 0; mt < 2; mt++) {
#pragma unroll
            for (int ks = 0; ks < 4; ks++) {
                ldsm4(qf[mt][ks], qb32 + ((wb + mt * 16 + lrA) * 36 + ks * 8 + kcA) * 4);
                float2 wA = wsc2[ks * 8 + c];
                float2 wB = wsc2[ks * 8 + 4 + c];
                qf[mt][ks][0] = scaleh2(qf[mt][ks][0], wA);
                qf[mt][ks][1] = scaleh2(qf[mt][ks][1], wA);
                qf[mt][ks][2] = scaleh2(qf[mt][ks][2], wB);
                qf[mt][ks][3] = scaleh2(qf[mt][ks][3], wB);
            }
        }
    }

    float O[2][9][4];
#pragma unroll
    for (int mt = 0; mt < 2; mt++)
#pragma unroll
        for (int dt = 0; dt < 9; dt++)
#pragma unroll
            for (int q = 0; q < 4; q++) O[mt][dt][q] = 0.f;

    for (int t = 0; t < 16; t++) {
        if (t == 15) { CP_WAIT(0); } else { CP_WAIT(1); }
        __syncthreads();
        if (t + 2 < 16) { load_kv((t + 2) * 64, (t + 2) % 3); CP_COMMIT(); }

        const uint32_t Kb32 = sbase + (t % 3) * KV_BUF * 4;
        const uint32_t Vb32 = Kb32 + 64 * 36 * 4;

        uint32_t S2[2][8][2];
#pragma unroll
        for (int mt = 0; mt < 2; mt++)
#pragma unroll
            for (int nt = 0; nt < 8; nt++) { S2[mt][nt][0] = 0u; S2[mt][nt][1] = 0u; }
#pragma unroll
        for (int ks = 0; ks < 4; ks++) {
#pragma unroll
            for (int np = 0; np < 4; np++) {
                uint32_t r[4];
                ldsm4(r, Kb32 + ((np * 16 + lrB) * 36 + ks * 8 + kcB) * 4);
                mma_f16_s16(S2[0][2 * np],     qf[0][ks], r);
                mma_f16_s16(S2[0][2 * np + 1], qf[0][ks], r + 2);
                mma_f16_s16(S2[1][2 * np],     qf[1][ks], r);
                mma_f16_s16(S2[1][2 * np + 1], qf[1][ks], r + 2);
            }
        }

#pragma unroll
        for (int mt = 0; mt < 2; mt++)
#pragma unroll
            for (int nt = 0; nt < 8; nt++) {
                S2[mt][nt][0] = ex2h2(S2[mt][nt][0]);
                S2[mt][nt][1] = ex2h2(S2[mt][nt][1]);
            }

#pragma unroll
        for (int jt = 0; jt < 4; jt++) {
            const uint32_t* a0 = &S2[0][2 * jt][0];
            const uint32_t* a1 = &S2[1][2 * jt][0];
#pragma unroll
            for (int dp = 0; dp < 4; dp++) {
                uint32_t r[4];
                ldsm4(r, Vb32 + ((dp * 16 + lrB) * 36 + jt * 8 + kcB) * 4);
                mma_f16(O[0][2 * dp], a0, r);
                mma_f16(O[0][2 * dp + 1], a0, r + 2);
                mma_f16(O[1][2 * dp], a1, r);
                mma_f16(O[1][2 * dp + 1], a1, r + 2);
            }
            mma_f16(O[0][8], a0, onesf);
            mma_f16(O[1][8], a1, onesf);
        }
    }
    __syncthreads();

    float il[2][2];
#pragma unroll
    for (int mt = 0; mt < 2; mt++) {
        il[mt][0] = 1.f / __shfl_sync(0xffffffffu, O[mt][8][0], lane & ~3);
        il[mt][1] = 1.f / __shfl_sync(0xffffffffu, O[mt][8][2], lane & ~3);
    }

    __half* Os = (__half*)smem;  // [64][136]
#pragma unroll
    for (int mt = 0; mt < 2; mt++) {
        int rb = wb + mt * 16;
#pragma unroll
        for (int dt = 0; dt < 8; dt++) {
            int d0 = dt * 8 + 2 * c;
            Os[d0 * 136 + rb + g]           = __float2half_rn(O[mt][dt][0] * il[mt][0]);
            Os[(d0 + 1) * 136 + rb + g]     = __float2half_rn(O[mt][dt][1] * il[mt][0]);
            Os[d0 * 136 + rb + g + 8]       = __float2half_rn(O[mt][dt][2] * il[mt][1]);
            Os[(d0 + 1) * 136 + rb + g + 8] = __float2half_rn(O[mt][dt][3] * il[mt][1]);
        }
    }
    __syncthreads();

#pragma unroll
    for (int rep = 0; rep < 8; rep++) {
        int lin = rep * 128 + tid;
        int d = lin >> 4, j = lin & 15;
        uint4* ob = (uint4*)(g_atth + (size_t)(b * HID_ + h * 64 + d) * N_ + i0);
        ob[j] = *(const uint4*)&Os[d * 136 + 8 * j];
    }
}

// ---------------------------------------------------------------------------
extern "C" void kernel_launch(void* const* d_in, const int* in_sizes, int n_in,
                              void* d_out, int out_size)
{
    (void)in_sizes; (void)n_in; (void)out_size;
    const float* x     = (const float*)d_in[0];
    const float* w_qkv = (const float*)d_in[1];
    const float* w_out = (const float*)d_in[2];
    const float* b_out = (const float*)d_in[3];
    float* y = (float*)d_out;

    cudaFuncSetAttribute((const void*)gemm_qkv,
                         cudaFuncAttributeMaxDynamicSharedMemorySize, G1_SMEM);
    cudaFuncSetAttribute((const void*)gemm_out,
                         cudaFuncAttributeMaxDynamicSharedMemorySize, G2_SMEM);
    cudaFuncSetAttribute((const void*)attn_fp16,
                         cudaFuncAttributeMaxDynamicSharedMemorySize, ATTN_SMEM_B);

    cvt_k<<<2048, 256>>>(x, w_qkv, w_out);
    gemm_qkv<<<dim3(N_ / 128, O3_ / 128, B_), 256, G1_SMEM>>>();
    attn_fp16<<<dim3(N_ / 128, H_, B_), 128, ATTN_SMEM_B>>>();
    gemm_out<<<dim3(N_ / 128, C_ / 64, B_), 256, G2_SMEM>>>(b_out, y);
}

// round 17
// speedup vs baseline: 1.0725x; 1.0493x over previous
#include <cuda_runtime.h>
#include <cuda_fp16.h>
#include <math.h>
#include <stdint.h>

#define B_    8
#define C_    256
#define N_    1024
#define H_    8
#define HID_  512
#define O3_   1536
#define SCALE_ 10.0f
#define EPS_   1e-12f
#define LOG2E_ 1.4426950408889634f

// Scratch (static device arrays; no allocation allowed)
__device__ float    g_sumsq[2 * B_ * HID_];
__device__ uint32_t g_xh[(size_t)B_ * C_ * N_ / 2];   // half2 x [b][c][p]
__device__ uint32_t g_wqh[O3_ * C_ / 2];              // half2 w_qkv [o][c]
__device__ uint32_t g_woh[C_ * HID_ / 2];             // half2 w_out [o][hid]
__device__ uint32_t g_qT[(size_t)B_ * H_ * N_ * 32];  // half2 q [b][h][i][d2]
__device__ uint32_t g_kT[(size_t)B_ * H_ * N_ * 32];  // half2 k [b][h][j][d2]
__device__ uint32_t g_vh[(size_t)B_ * H_ * 64 * 512]; // half2 v [b][h][d][j2]
__device__ __half   g_atth[(size_t)B_ * HID_ * N_];   // half attn out [b][hid][p]

__device__ __forceinline__ uint32_t packh2(float lo, float hi) {
    __half2 h = __floats2half2_rn(lo, hi);
    return *(uint32_t*)&h;
}
__device__ __forceinline__ uint32_t scaleh2(uint32_t v, float2 w) {
    __half2 h = *(__half2*)&v;
    float2 f = __half22float2(h);
    return packh2(f.x * w.x, f.y * w.y);
}
__device__ __forceinline__ uint32_t ex2h2(uint32_t x) {
    uint32_t r; asm("ex2.approx.f16x2 %0, %1;" : "=r"(r) : "r"(x)); return r;
}
__device__ __forceinline__ void mma_f16(float* d, const uint32_t* a, const uint32_t* b) {
    asm volatile("mma.sync.aligned.m16n8k16.row.col.f32.f16.f16.f32 "
                 "{%0,%1,%2,%3}, {%4,%5,%6,%7}, {%8,%9}, {%0,%1,%2,%3};\n"
                 : "+f"(d[0]), "+f"(d[1]), "+f"(d[2]), "+f"(d[3])
                 : "r"(a[0]), "r"(a[1]), "r"(a[2]), "r"(a[3]),
                   "r"(b[0]), "r"(b[1]));
}
// f16-accumulator mma: D (2x half2 regs) has exactly the A-fragment layout
__device__ __forceinline__ void mma_f16_s16(uint32_t* d, const uint32_t* a, const uint32_t* b) {
    asm volatile("mma.sync.aligned.m16n8k16.row.col.f16.f16.f16.f16 "
                 "{%0,%1}, {%2,%3,%4,%5}, {%6,%7}, {%0,%1};\n"
                 : "+r"(d[0]), "+r"(d[1])
                 : "r"(a[0]), "r"(a[1]), "r"(a[2]), "r"(a[3]),
                   "r"(b[0]), "r"(b[1]));
}
__device__ __forceinline__ void ldsm4(uint32_t* r, uint32_t saddr) {
    asm volatile("ldmatrix.sync.aligned.m8n8.x4.shared.b16 {%0,%1,%2,%3}, [%4];"
                 : "=r"(r[0]), "=r"(r[1]), "=r"(r[2]), "=r"(r[3]) : "r"(saddr));
}
__device__ __forceinline__ void ldsm4t(uint32_t* r, uint32_t saddr) {
    asm volatile("ldmatrix.sync.aligned.m8n8.x4.trans.shared.b16 {%0,%1,%2,%3}, [%4];"
                 : "=r"(r[0]), "=r"(r[1]), "=r"(r[2]), "=r"(r[3]) : "r"(saddr));
}
__device__ __forceinline__ void cpa16(void* dst, const void* src) {
    uint32_t d = (uint32_t)__cvta_generic_to_shared(dst);
    asm volatile("cp.async.cg.shared.global [%0], [%1], 16;" :: "r"(d), "l"(src));
}
#define CP_COMMIT() asm volatile("cp.async.commit_group;")
#define CP_WAIT(n)  asm volatile("cp.async.wait_group %0;" :: "n"(n))

// ---------------------------------------------------------------------------
// fp16 conversion of inputs + zero sumsq accumulators (float4 vectorized).
// ---------------------------------------------------------------------------
__global__ void __launch_bounds__(256) cvt_k(const float* __restrict__ x,
                                             const float* __restrict__ wq,
                                             const float* __restrict__ wo)
{
    const int i = blockIdx.x * 256 + threadIdx.x;
    const int stride = gridDim.x * 256;
    for (int t = i; t < 2 * B_ * HID_; t += stride) g_sumsq[t] = 0.f;
    for (int t = i; t < B_ * C_ * N_ / 4; t += stride) {
        float4 v = ((const float4*)x)[t];
        ((uint2*)g_xh)[t] = make_uint2(packh2(v.x, v.y), packh2(v.z, v.w));
    }
    for (int t = i; t < O3_ * C_ / 4; t += stride) {
        float4 v = ((const float4*)wq)[t];
        ((uint2*)g_wqh)[t] = make_uint2(packh2(v.x, v.y), packh2(v.z, v.w));
    }
    for (int t = i; t < C_ * HID_ / 4; t += stride) {
        float4 v = ((const float4*)wo)[t];
        ((uint2*)g_woh)[t] = make_uint2(packh2(v.x, v.y), packh2(v.z, v.w));
    }
}

// ---------------------------------------------------------------------------
// QKV projection (fp16 mma), 3-stage cp.async ring — R10 exact.
// Fused epilogue: q,k -> fp16 [token][d] + sumsq atomics; v -> [d][token].
// ---------------------------------------------------------------------------
#define G1_ASZ (128 * 40)
#define G1_BSZ (32 * 136)
#define G1_STG (G1_ASZ + G1_BSZ)
#define G1_SMEM (3 * G1_STG * 2)

__global__ void __launch_bounds__(256) gemm_qkv()
{
    extern __shared__ __half hsm[];

    const int b = blockIdx.z;
    const int o0 = blockIdx.y * 128;
    const int p0 = blockIdx.x * 128;
    const __half* W = (const __half*)g_wqh;
    const __half* Xb = (const __half*)g_xh + (size_t)b * C_ * N_;

    const int tid = threadIdx.x, warp = tid >> 5, lane = tid & 31;
    const int g = lane >> 2, c = lane & 3;
    const int wmb = (warp >> 2) * 64;
    const int wnb = (warp & 3) * 32;
    const int lr = (lane & 7) + ((lane >> 3) & 1) * 8;
    const int hc = (lane >> 4) * 8;

    float acc[4][4][4];
#pragma unroll
    for (int mt = 0; mt < 4; mt++)
#pragma unroll
        for (int nt = 0; nt < 4; nt++)
#pragma unroll
            for (int q = 0; q < 4; q++) acc[mt][nt][q] = 0.f;

    auto load_tile = [&](int k0, int st) {
        __half* A = hsm + st * G1_STG;
        __half* Bs = A + G1_ASZ;
#pragma unroll
        for (int rep = 0; rep < 2; rep++) {
            int lin = rep * 256 + tid;
            int m = lin >> 2, ch = lin & 3;
            cpa16(A + m * 40 + ch * 8, W + (size_t)(o0 + m) * C_ + k0 + ch * 8);
        }
#pragma unroll
        for (int rep = 0; rep < 2; rep++) {
            int lin = rep * 256 + tid;
            int k = lin >> 4, ch = lin & 15;
            cpa16(Bs + k * 136 + ch * 8, Xb + (size_t)(k0 + k) * N_ + p0 + ch * 8);
        }
    };

    load_tile(0, 0); CP_COMMIT();
    load_tile(32, 1); CP_COMMIT();
    const int T = C_ / 32;
    for (int t = 0; t < T; t++) {
        if (t == T - 1) { CP_WAIT(0); } else { CP_WAIT(1); }
        __syncthreads();
        uint32_t ab = (uint32_t)__cvta_generic_to_shared(hsm + (t % 3) * G1_STG);
        uint32_t bb = ab + G1_ASZ * 2;
#pragma unroll
        for (int ks = 0; ks < 2; ks++) {
            uint32_t a[4][4];
#pragma unroll
            for (int mt = 0; mt < 4; mt++)
                ldsm4(a[mt], ab + ((wmb + mt * 16 + lr) * 40 + ks * 16 + hc) * 2);
            uint32_t bf[4][2];
#pragma unroll
            for (int np = 0; np < 2; np++) {
                uint32_t r[4];
                ldsm4t(r, bb + ((ks * 16 + lr) * 136 + wnb + np * 16 + hc) * 2);
                bf[2 * np][0] = r[0]; bf[2 * np][1] = r[1];
                bf[2 * np + 1][0] = r[2]; bf[2 * np + 1][1] = r[3];
            }
#pragma unroll
            for (int nt = 0; nt < 4; nt++)
#pragma unroll
                for (int mt = 0; mt < 4; mt++)
                    mma_f16(acc[mt][nt], a[mt], bf[nt]);
            // defer prefetch until after first compute burst
            if (ks == 0 && t + 2 < T) { load_tile((t + 2) * 32, (t + 2) % 3); CP_COMMIT(); }
        }
    }
    __syncthreads();

    const int type = blockIdx.y >> 2;
    const int h0 = (blockIdx.y & 3) * 2;

    if (type == 2) {
#pragma unroll
        for (int mt = 0; mt < 4; mt++) {
#pragma unroll
            for (int nt = 0; nt < 4; nt++) {
                int pc2 = (p0 + wnb + nt * 8) / 2 + c;
                int ol = wmb + mt * 16 + g;
                int ha = ol >> 6, da = ol & 63;
                g_vh[((size_t)(b * H_ + h0 + ha) * 64 + da) * 512 + pc2] =
                    packh2(acc[mt][nt][0], acc[mt][nt][1]);
                int ol8 = ol + 8;
                int hb = ol8 >> 6, db = ol8 & 63;
                g_vh[((size_t)(b * H_ + h0 + hb) * 64 + db) * 512 + pc2] =
                    packh2(acc[mt][nt][2], acc[mt][nt][3]);
            }
        }
        return;
    }

    const int sbase = type * (B_ * HID_) + b * HID_ + (blockIdx.y & 3) * 128;
#pragma unroll
    for (int mt = 0; mt < 4; mt++) {
        float s0 = 0.f, s1 = 0.f;
#pragma unroll
        for (int nt = 0; nt < 4; nt++) {
            s0 = fmaf(acc[mt][nt][0], acc[mt][nt][0], s0);
            s0 = fmaf(acc[mt][nt][1], acc[mt][nt][1], s0);
            s1 = fmaf(acc[mt][nt][2], acc[mt][nt][2], s1);
            s1 = fmaf(acc[mt][nt][3], acc[mt][nt][3], s1);
        }
        s0 += __shfl_xor_sync(0xffffffffu, s0, 1);
        s0 += __shfl_xor_sync(0xffffffffu, s0, 2);
        s1 += __shfl_xor_sync(0xffffffffu, s1, 1);
        s1 += __shfl_xor_sync(0xffffffffu, s1, 2);
        if (c == 0) {
            int ol = wmb + mt * 16 + g;
            atomicAdd(&g_sumsq[sbase + ol], s0);
            atomicAdd(&g_sumsq[sbase + ol + 8], s1);
        }
    }

    __half* trs = hsm;  // [128 p][136]
#pragma unroll
    for (int mt = 0; mt < 4; mt++) {
#pragma unroll
        for (int nt = 0; nt < 4; nt++) {
            int ol = wmb + mt * 16 + g;
            int pc = wnb + nt * 8 + 2 * c;
            trs[pc * 136 + ol]           = __float2half_rn(acc[mt][nt][0]);
            trs[(pc + 1) * 136 + ol]     = __float2half_rn(acc[mt][nt][1]);
            trs[pc * 136 + ol + 8]       = __float2half_rn(acc[mt][nt][2]);
            trs[(pc + 1) * 136 + ol + 8] = __float2half_rn(acc[mt][nt][3]);
        }
    }
    __syncthreads();

    uint32_t* dst = (type == 0) ? g_qT : g_kT;
#pragma unroll
    for (int rep = 0; rep < 32; rep++) {
        int lin = rep * 256 + tid;
        int d2 = lin & 31, hh = (lin >> 5) & 1, p = lin >> 6;
        dst[((size_t)(b * H_ + h0 + hh) * N_ + p0 + p) * 32 + d2] =
            *(const uint32_t*)&trs[p * 136 + hh * 64 + 2 * d2];
    }
}

// ---------------------------------------------------------------------------
// Output projection (fp16 mma), BM=64 x BN=128, KT=32, 3-stage ring,
// prefetch distance 2, prefetch deferred past first compute burst.
// ---------------------------------------------------------------------------
#define G2_ASZ (64 * 40)
#define G2_BSZ (32 * 136)
#define G2_STG (G2_ASZ + G2_BSZ)
#define G2_SMEM (3 * G2_STG * 2)

__global__ void __launch_bounds__(256) gemm_out(const float* __restrict__ bias,
                                                float* __restrict__ Y)
{
    extern __shared__ __half hsm[];

    const int b = blockIdx.z;
    const int o0 = blockIdx.y * 64;
    const int p0 = blockIdx.x * 128;
    const __half* W = (const __half*)g_woh;
    const __half* Xb = g_atth + (size_t)b * HID_ * N_;
    float* Yb = Y + (size_t)b * C_ * N_;

    const int tid = threadIdx.x, warp = tid >> 5, lane = tid & 31;
    const int g = lane >> 2, c = lane & 3;
    const int wmb = (warp >> 2) * 32;
    const int wnb = (warp & 3) * 32;
    const int lr = (lane & 7) + ((lane >> 3) & 1) * 8;
    const int hc = (lane >> 4) * 8;

    float acc[2][4][4];
#pragma unroll
    for (int mt = 0; mt < 2; mt++)
#pragma unroll
        for (int nt = 0; nt < 4; nt++)
#pragma unroll
            for (int q = 0; q < 4; q++) acc[mt][nt][q] = 0.f;

    auto load_tile = [&](int k0, int st) {
        __half* A = hsm + st * G2_STG;
        __half* Bs = A + G2_ASZ;
        {
            int m = tid >> 2, ch = tid & 3;
            cpa16(A + m * 40 + ch * 8, W + (size_t)(o0 + m) * HID_ + k0 + ch * 8);
        }
#pragma unroll
        for (int rep = 0; rep < 2; rep++) {
            int lin = rep * 256 + tid;
            int k = lin >> 4, ch = lin & 15;
            cpa16(Bs + k * 136 + ch * 8, Xb + (size_t)(k0 + k) * N_ + p0 + ch * 8);
        }
    };

    load_tile(0, 0); CP_COMMIT();
    load_tile(32, 1); CP_COMMIT();
    const int T = HID_ / 32;
    for (int t = 0; t < T; t++) {
        if (t == T - 1) { CP_WAIT(0); } else { CP_WAIT(1); }
        __syncthreads();
        uint32_t ab = (uint32_t)__cvta_generic_to_shared(hsm + (t % 3) * G2_STG);
        uint32_t bb = ab + G2_ASZ * 2;
#pragma unroll
        for (int ks = 0; ks < 2; ks++) {
            uint32_t a[2][4];
#pragma unroll
            for (int mt = 0; mt < 2; mt++)
                ldsm4(a[mt], ab + ((wmb + mt * 16 + lr) * 40 + ks * 16 + hc) * 2);
            uint32_t bf[4][2];
#pragma unroll
            for (int np = 0; np < 2; np++) {
                uint32_t r[4];
                ldsm4t(r, bb + ((ks * 16 + lr) * 136 + wnb + np * 16 + hc) * 2);
                bf[2 * np][0] = r[0]; bf[2 * np][1] = r[1];
                bf[2 * np + 1][0] = r[2]; bf[2 * np + 1][1] = r[3];
            }
#pragma unroll
            for (int nt = 0; nt < 4; nt++)
#pragma unroll
                for (int mt = 0; mt < 2; mt++)
                    mma_f16(acc[mt][nt], a[mt], bf[nt]);
            if (ks == 0 && t + 2 < T) { load_tile((t + 2) * 32, (t + 2) % 3); CP_COMMIT(); }
        }
    }

#pragma unroll
    for (int mt = 0; mt < 2; mt++) {
        int r0 = o0 + wmb + mt * 16 + g;
        float bv0 = bias[r0];
        float bv1 = bias[r0 + 8];
#pragma unroll
        for (int nt = 0; nt < 4; nt++) {
            int col = p0 + wnb + nt * 8 + 2 * c;
            *(float2*)(Yb + (size_t)r0 * N_ + col) =
                make_float2(acc[mt][nt][0] + bv0, acc[mt][nt][1] + bv0);
            *(float2*)(Yb + (size_t)(r0 + 8) * N_ + col) =
                make_float2(acc[mt][nt][2] + bv1, acc[mt][nt][3] + bv1);
        }
    }
}

// ---------------------------------------------------------------------------
// Fused flash attention, fp16 m16n8k16, 4 warps x 32 query rows.
// 3-stage K/V ring, ONE barrier per tile, prefetch deferred past S-phase.
// Ones B-fragment in registers (row sums l).
// ---------------------------------------------------------------------------
#define KV_BUF (128 * 36)
#define ATTN_SMEM_B (3 * KV_BUF * 4)

__global__ void __launch_bounds__(128, 3) attn_fp16()
{
    extern __shared__ uint32_t smem[];
    __shared__ float wsc_s[64];

    const int b = blockIdx.z, h = blockIdx.y, i0 = blockIdx.x * 128;
    const uint32_t* qTb = g_qT + (size_t)(b * H_ + h) * N_ * 32;
    const uint32_t* kTb = g_kT + (size_t)(b * H_ + h) * N_ * 32;
    const uint32_t* vhb = g_vh + (size_t)(b * H_ + h) * 64 * 512;

    const int tid = threadIdx.x;
    const int warp = tid >> 5, lane = tid & 31;
    const int g = lane >> 2, c = lane & 3;
    const int wb = warp * 32;
    const int lrB = (lane & 7) + (lane >> 4) * 8;
    const int kcB = ((lane >> 3) & 1) * 4;
    const int lrA = (lane & 7) + ((lane >> 3) & 1) * 8;
    const int kcA = (lane >> 4) * 4;

    const uint32_t sbase = (uint32_t)__cvta_generic_to_shared(smem);

    uint32_t onesf[2];
    onesf[0] = onesf[1] = (g == 0) ? 0x3C003C00u : 0u;

    auto load_kv = [&](int j0, int st) {
        uint32_t* K = smem + st * KV_BUF;
        uint32_t* V = K + 64 * 36;
#pragma unroll
        for (int rep = 0; rep < 4; rep++) {
            int lin = rep * 128 + tid;
            int r = lin >> 3, sg = (lin & 7) * 4;
            cpa16(&K[r * 36 + sg], kTb + (size_t)(j0 + r) * 32 + sg);
        }
#pragma unroll
        for (int rep = 0; rep < 4; rep++) {
            int lin = rep * 128 + tid;
            int r = lin >> 3, sg = (lin & 7) * 4;
            cpa16(&V[r * 36 + sg], vhb + (size_t)r * 512 + j0 / 2 + sg);
        }
    };

    uint32_t* Qst = smem + 2 * KV_BUF;
#pragma unroll
    for (int rep = 0; rep < 8; rep++) {
        int lin = rep * 128 + tid;
        int i = lin >> 3, sg = (lin & 7) * 4;
        cpa16(&Qst[i * 36 + sg], qTb + (size_t)(i0 + i) * 32 + sg);
    }
    CP_COMMIT();
    load_kv(0, 0); CP_COMMIT();
    load_kv(64, 1); CP_COMMIT();
    if (tid < 64) {
        float qs = g_sumsq[b * HID_ + h * 64 + tid];
        float ks = g_sumsq[B_ * HID_ + b * HID_ + h * 64 + tid];
        wsc_s[tid] = (SCALE_ * LOG2E_) /
                     (fmaxf(sqrtf(qs), EPS_) * fmaxf(sqrtf(ks), EPS_));
    }
    CP_WAIT(2);
    __syncthreads();

    uint32_t qf[2][4][4];
    {
        const uint32_t qb32 = sbase + 2 * KV_BUF * 4;
        const float2* wsc2 = (const float2*)wsc_s;
#pragma unroll
        for (int mt = 0; mt < 2; mt++) {
#pragma unroll
            for (int ks = 0; ks < 4; ks++) {
                ldsm4(qf[mt][ks], qb32 + ((wb + mt * 16 + lrA) * 36 + ks * 8 + kcA) * 4);
                float2 wA = wsc2[ks * 8 + c];
                float2 wB = wsc2[ks * 8 + 4 + c];
                qf[mt][ks][0] = scaleh2(qf[mt][ks][0], wA);
                qf[mt][ks][1] = scaleh2(qf[mt][ks][1], wA);
                qf[mt][ks][2] = scaleh2(qf[mt][ks][2], wB);
                qf[mt][ks][3] = scaleh2(qf[mt][ks][3], wB);
            }
        }
    }

    float O[2][9][4];
#pragma unroll
    for (int mt = 0; mt < 2; mt++)
#pragma unroll
        for (int dt = 0; dt < 9; dt++)
#pragma unroll
            for (int q = 0; q < 4; q++) O[mt][dt][q] = 0.f;

    for (int t = 0; t < 16; t++) {
        if (t == 15) { CP_WAIT(0); } else { CP_WAIT(1); }
        __syncthreads();

        const uint32_t Kb32 = sbase + (t % 3) * KV_BUF * 4;
        const uint32_t Vb32 = Kb32 + 64 * 36 * 4;

        // S = Q.K^T, fp16 accumulators; ldsm-then-consume
        uint32_t S2[2][8][2];
#pragma unroll
        for (int mt = 0; mt < 2; mt++)
#pragma unroll
            for (int nt = 0; nt < 8; nt++) { S2[mt][nt][0] = 0u; S2[mt][nt][1] = 0u; }
#pragma unroll
        for (int ks = 0; ks < 4; ks++) {
#pragma unroll
            for (int np = 0; np < 4; np++) {
                uint32_t r[4];
                ldsm4(r, Kb32 + ((np * 16 + lrB) * 36 + ks * 8 + kcB) * 4);
                mma_f16_s16(S2[0][2 * np],     qf[0][ks], r);
                mma_f16_s16(S2[0][2 * np + 1], qf[0][ks], r + 2);
                mma_f16_s16(S2[1][2 * np],     qf[1][ks], r);
                mma_f16_s16(S2[1][2 * np + 1], qf[1][ks], r + 2);
            }
        }

        // prefetch issued after the S mma burst (tensor stream restarts first)
        if (t + 2 < 16) { load_kv((t + 2) * 64, (t + 2) % 3); CP_COMMIT(); }

        // P = exp2(S) in place
#pragma unroll
        for (int mt = 0; mt < 2; mt++)
#pragma unroll
            for (int nt = 0; nt < 8; nt++) {
                S2[mt][nt][0] = ex2h2(S2[mt][nt][0]);
                S2[mt][nt][1] = ex2h2(S2[mt][nt][1]);
            }

        // O += P.V; dt=8 via register ones-fragment (row sums l)
#pragma unroll
        for (int jt = 0; jt < 4; jt++) {
            const uint32_t* a0 = &S2[0][2 * jt][0];
            const uint32_t* a1 = &S2[1][2 * jt][0];
#pragma unroll
            for (int dp = 0; dp < 4; dp++) {
                uint32_t r[4];
                ldsm4(r, Vb32 + ((dp * 16 + lrB) * 36 + jt * 8 + kcB) * 4);
                mma_f16(O[0][2 * dp], a0, r);
                mma_f16(O[0][2 * dp + 1], a0, r + 2);
                mma_f16(O[1][2 * dp], a1, r);
                mma_f16(O[1][2 * dp + 1], a1, r + 2);
            }
            mma_f16(O[0][8], a0, onesf);
            mma_f16(O[1][8], a1, onesf);
        }
    }
    __syncthreads();

    float il[2][2];
#pragma unroll
    for (int mt = 0; mt < 2; mt++) {
        il[mt][0] = 1.f / __shfl_sync(0xffffffffu, O[mt][8][0], lane & ~3);
        il[mt][1] = 1.f / __shfl_sync(0xffffffffu, O[mt][8][2], lane & ~3);
    }

    __half* Os = (__half*)smem;  // [64][136]
#pragma unroll
    for (int mt = 0; mt < 2; mt++) {
        int rb = wb + mt * 16;
#pragma unroll
        for (int dt = 0; dt < 8; dt++) {
            int d0 = dt * 8 + 2 * c;
            Os[d0 * 136 + rb + g]           = __float2half_rn(O[mt][dt][0] * il[mt][0]);
            Os[(d0 + 1) * 136 + rb + g]     = __float2half_rn(O[mt][dt][1] * il[mt][0]);
            Os[d0 * 136 + rb + g + 8]       = __float2half_rn(O[mt][dt][2] * il[mt][1]);
            Os[(d0 + 1) * 136 + rb + g + 8] = __float2half_rn(O[mt][dt][3] * il[mt][1]);
        }
    }
    __syncthreads();

#pragma unroll
    for (int rep = 0; rep < 8; rep++) {
        int lin = rep * 128 + tid;
        int d = lin >> 4, j = lin & 15;
        uint4* ob = (uint4*)(g_atth + (size_t)(b * HID_ + h * 64 + d) * N_ + i0);
        ob[j] = *(const uint4*)&Os[d * 136 + 8 * j];
    }
}

// ---------------------------------------------------------------------------
extern "C" void kernel_launch(void* const* d_in, const int* in_sizes, int n_in,
                              void* d_out, int out_size)
{
    (void)in_sizes; (void)n_in; (void)out_size;
    const float* x     = (const float*)d_in[0];
    const float* w_qkv = (const float*)d_in[1];
    const float* w_out = (const float*)d_in[2];
    const float* b_out = (const float*)d_in[3];
    float* y = (float*)d_out;

    cudaFuncSetAttribute((const void*)gemm_qkv,
                         cudaFuncAttributeMaxDynamicSharedMemorySize, G1_SMEM);
    cudaFuncSetAttribute((const void*)gemm_out,
                         cudaFuncAttributeMaxDynamicSharedMemorySize, G2_SMEM);
    cudaFuncSetAttribute((const void*)attn_fp16,
                         cudaFuncAttributeMaxDynamicSharedMemorySize, ATTN_SMEM_B);

    cvt_k<<<2048, 256>>>(x, w_qkv, w_out);
    gemm_qkv<<<dim3(N_ / 128, O3_ / 128, B_), 256, G1_SMEM>>>();
    attn_fp16<<<dim3(N_ / 128, H_, B_), 128, ATTN_SMEM_B>>>();
    gemm_out<<<dim3(N_ / 128, C_ / 64, B_), 256, G2_SMEM>>>(b_out, y);
}